// round 6
// baseline (speedup 1.0000x reference)
#include <cuda_runtime.h>
#include <math.h>

// Problem constants
#define BB   64      // batch
#define TT   128     // seq len
#define FF   16      // features
#define HH   512     // hidden
#define NSEQ 128     // B * S (2 segments batched)
#define G4   2048    // 4*H gate rows

// ---------------- scratch (__device__ globals; no allocations) ----------------
__device__ float g_temb[8192 * 1024];              // [n=b*T+t][1024] timestep embeddings
__device__ float g_gin [(size_t)128 * 2048 * 128]; // [t2][r][seq] fused input gates (+biases)
__device__ float g_hh  [(size_t)128 * 512 * 128];  // [t2][k][seq] h history
__device__ float g_h   [512 * 128];                // [k][seq] current h
__device__ float g_c   [512 * 128];                // [k][seq] current c
__device__ float g_M   [14 * 2048];                // folded small-input matrices (e0 rows 0..7, e1 rows 8..13)
__device__ float g_cst [2 * 2048];                 // folded constants per input-segment

__device__ __forceinline__ float sigf(float x) { return 1.0f / (1.0f + expf(-x)); }

// ---------------- K0: fold W_is / biases into M and const ----------------
__global__ void k_prep(const float* __restrict__ Wis0, const float* __restrict__ bis0,
                       const float* __restrict__ Wis1, const float* __restrict__ bis1,
                       const float* __restrict__ Wih,  const float* __restrict__ bih,
                       const float* __restrict__ bhh) {
    int r   = blockIdx.x;          // gate row 0..2047
    int tid = threadIdx.x;         // 128
    float acc[16];
#pragma unroll
    for (int j = 0; j < 16; j++) acc[j] = 0.0f;
    const float* wr = Wih + (size_t)r * 1536;      // W_ih row r, cols 0..511 used here
    for (int k = tid; k < 512; k += 128) {
        float w = wr[k];
#pragma unroll
        for (int j = 0; j < 8; j++) acc[j]     += Wis0[k * 8 + j] * w;
#pragma unroll
        for (int j = 0; j < 6; j++) acc[8 + j] += Wis1[k * 6 + j] * w;
        acc[14] += bis0[k] * w;
        acc[15] += bis1[k] * w;
    }
    __shared__ float red[16][128];
#pragma unroll
    for (int j = 0; j < 16; j++) red[j][tid] = acc[j];
    __syncthreads();
    for (int s = 64; s > 0; s >>= 1) {
        if (tid < s) {
#pragma unroll
            for (int j = 0; j < 16; j++) red[j][tid] += red[j][tid + s];
        }
        __syncthreads();
    }
    if (tid < 14) g_M[tid * 2048 + r] = red[tid][0];
    if (tid == 14) g_cst[r]        = red[14][0] + bih[r] + bhh[r];
    if (tid == 15) g_cst[2048 + r] = red[15][0] + bih[r] + bhh[r];
}

// ---------------- K1: init h/c (both LSTM segments share h0/c0), seq-minor layout ----------------
__global__ void k_init(const float* __restrict__ h0, const float* __restrict__ c0) {
    int idx = blockIdx.x * blockDim.x + threadIdx.x;   // over 512*64
    if (idx >= 512 * 64) return;
    int k = idx >> 6, b = idx & 63;
    float hv = h0[b * 512 + k], cv = c0[b * 512 + k];
    g_h[k * 128 + b]      = hv;  g_h[k * 128 + 64 + b] = hv;
    g_c[k * 128 + b]      = cv;  g_c[k * 128 + 64 + b] = cv;
}

// ---------------- K2: timestep embeddings (cos|sin for both time columns) ----------------
__global__ void k_temb(const float* __restrict__ x) {
    int n = blockIdx.x;          // 0..8191 (= b*128 + t)
    int i = threadIdx.x;         // 0..255
    float tc = x[n * 16 + 0];
    float tp = x[n * 16 + 1];
    float f  = expf(-9.210340371976184f * (float)i * (1.0f / 256.0f)); // ln(10000)
    float s, c;
    float* row = g_temb + (size_t)n * 1024;
    sincosf(tc * f, &s, &c);
    row[i]       = c;  row[256 + i] = s;
    sincosf(tp * f, &s, &c);
    row[512 + i] = c;  row[768 + i] = s;
}

// ---------------- K3: big GEMM  g_in = t_emb @ W_ih[:,512:1536].T  + small-rank epilogue ----------------
// M=8192 (n = b*128+t), N=2048 (gate rows), K=1024. Tiles 128x128x8, 256 threads, 8x8 per thread.
//
// torch reshape semantics: concat([e0,e1],dim=1) -> [B*T,2,3H] -> reshape(B,2,T,3H).
// Element (orig_t=t, input_seg=s) lands at LSTM segment s2 = t>>6, step t2 = 2*(t&63)+s.
__global__ __launch_bounds__(256, 2) void k_gemm(const float* __restrict__ x,
                                                 const float* __restrict__ Wih) {
    __shared__ float As[8][132];
    __shared__ float Bs[8][132];
    int bx = blockIdx.x;               // 0..15  (N tiles)
    int by = blockIdx.y;               // 0..63  (M tiles == batch b)
    int tid = threadIdx.x;
    int tx = tid & 15, ty = tid >> 4;  // 16x16 thread grid, 8x8 outputs each
    int lrow = tid >> 1;               // 0..127
    int lq   = (tid & 1) * 4;          // 0 or 4
    const float* Ag = g_temb + ((size_t)(by * 128 + lrow)) * 1024 + lq;
    const float* Bg = Wih    + ((size_t)(bx * 128 + lrow)) * 1536 + 512 + lq;

    float acc[8][8];
#pragma unroll
    for (int i = 0; i < 8; i++)
#pragma unroll
        for (int j = 0; j < 8; j++) acc[i][j] = 0.0f;

    for (int kt = 0; kt < 1024; kt += 8) {
        float4 a4 = *(const float4*)(Ag + kt);
        float4 b4 = *(const float4*)(Bg + kt);
        As[lq + 0][lrow] = a4.x; As[lq + 1][lrow] = a4.y;
        As[lq + 2][lrow] = a4.z; As[lq + 3][lrow] = a4.w;
        Bs[lq + 0][lrow] = b4.x; Bs[lq + 1][lrow] = b4.y;
        Bs[lq + 2][lrow] = b4.z; Bs[lq + 3][lrow] = b4.w;
        __syncthreads();
#pragma unroll
        for (int kk = 0; kk < 8; kk++) {
            float a[8], b[8];
#pragma unroll
            for (int i = 0; i < 8; i++) a[i] = As[kk][ty * 8 + i];
#pragma unroll
            for (int j = 0; j < 8; j++) b[j] = Bs[kk][tx * 8 + j];
#pragma unroll
            for (int i = 0; i < 8; i++)
#pragma unroll
                for (int j = 0; j < 8; j++) acc[i][j] += a[i] * b[j];
        }
        __syncthreads();
    }

    // Epilogue: add folded small-input term + constants; scatter per torch reshape.
    // g_gin layout: [t2][r][seq], seq = s2*64 + b  (coalesced for the recurrent reader)
#pragma unroll
    for (int i = 0; i < 8; i++) {
        int t = ty * 8 + i;                      // original timestep
        int s2 = t >> 6;                         // LSTM segment
        int t0 = 2 * (t & 63);                   // LSTM step for input-seg 0 (v1 -> t0+1)
        int seq = s2 * 64 + by;
        const float* xr = x + ((size_t)by * 128 + t) * 16 + 2;
        float xs[14];
#pragma unroll
        for (int jj = 0; jj < 14; jj++) xs[jj] = xr[jj];
#pragma unroll
        for (int j = 0; j < 8; j++) {
            int r = bx * 128 + tx * 8 + j;
            float base = acc[i][j];
            float v0 = base + g_cst[r];
            float v1 = base + g_cst[2048 + r];
#pragma unroll
            for (int jj = 0; jj < 8; jj++) v0 += xs[jj] * g_M[jj * 2048 + r];
#pragma unroll
            for (int jj = 0; jj < 6; jj++) v1 += xs[8 + jj] * g_M[(8 + jj) * 2048 + r];
            g_gin[((size_t)t0 * 2048 + r) * 128 + seq]       = v0;
            g_gin[((size_t)(t0 + 1) * 2048 + r) * 128 + seq] = v1;
        }
    }
}

// ---------------- K4: one LSTM step. 128 blocks, each owns 4 hidden units for all 128 seqs ----------------
__global__ __launch_bounds__(128) void k_step(const float* __restrict__ Whh, int t) {
    __shared__ float Wsm[16][512];   // rows: gr = gate*4 + u   (32 KB)
    __shared__ float gsm[16][128];   // Wh·h partials [gr][seq] (8 KB)
    int j4   = blockIdx.x * 4;       // hidden unit base
    int tid  = threadIdx.x;          // 128
    int w    = tid >> 5;             // warp == gate index 0..3
    int lane = tid & 31;

    // Load 16 W_hh rows into smem (rows: gate*512 + j4 + u)
#pragma unroll
    for (int gr = 0; gr < 16; gr++) {
        int grow = (gr >> 2) * 512 + j4 + (gr & 3);
        *(float4*)&Wsm[gr][tid * 4] = *(const float4*)(Whh + (size_t)grow * 512 + tid * 4);
    }
    __syncthreads();

    // gates_wh[gr][seq] = sum_k Wsm[gr][k] * h[k][seq]; lane handles seqs 4*lane..4*lane+3
    float a0[4] = {0,0,0,0}, a1[4] = {0,0,0,0}, a2[4] = {0,0,0,0}, a3[4] = {0,0,0,0};
    int w4 = w * 4;
#pragma unroll 8
    for (int k = 0; k < 512; k++) {
        float4 hv = *(const float4*)(g_h + k * 128 + 4 * lane);
        float w0 = Wsm[w4 + 0][k], w1 = Wsm[w4 + 1][k];
        float w2 = Wsm[w4 + 2][k], w3 = Wsm[w4 + 3][k];
        a0[0] += w0 * hv.x; a0[1] += w0 * hv.y; a0[2] += w0 * hv.z; a0[3] += w0 * hv.w;
        a1[0] += w1 * hv.x; a1[1] += w1 * hv.y; a1[2] += w1 * hv.z; a1[3] += w1 * hv.w;
        a2[0] += w2 * hv.x; a2[1] += w2 * hv.y; a2[2] += w2 * hv.z; a2[3] += w2 * hv.w;
        a3[0] += w3 * hv.x; a3[1] += w3 * hv.y; a3[2] += w3 * hv.z; a3[3] += w3 * hv.w;
    }
    *(float4*)&gsm[w4 + 0][4 * lane] = make_float4(a0[0], a0[1], a0[2], a0[3]);
    *(float4*)&gsm[w4 + 1][4 * lane] = make_float4(a1[0], a1[1], a1[2], a1[3]);
    *(float4*)&gsm[w4 + 2][4 * lane] = make_float4(a2[0], a2[1], a2[2], a2[3]);
    *(float4*)&gsm[w4 + 3][4 * lane] = make_float4(a3[0], a3[1], a3[2], a3[3]);
    __syncthreads();

    // Update phase: thread (u = tid>>5) handles unit j4+u, seqs 4*lane..+3
    int u  = tid >> 5;
    int l4 = 4 * lane;
    int hu = j4 + u;
    float4 gi = *(float4*)&gsm[u][l4];
    float4 gf = *(float4*)&gsm[4 + u][l4];
    float4 gg = *(float4*)&gsm[8 + u][l4];
    float4 go = *(float4*)&gsm[12 + u][l4];
    const float* ginb = g_gin + (size_t)t * 2048 * 128;
    float4 xi = *(const float4*)(ginb + ((size_t)(0    + hu)) * 128 + l4);
    float4 xf = *(const float4*)(ginb + ((size_t)(512  + hu)) * 128 + l4);
    float4 xg = *(const float4*)(ginb + ((size_t)(1024 + hu)) * 128 + l4);
    float4 xo = *(const float4*)(ginb + ((size_t)(1536 + hu)) * 128 + l4);
    float4 cv = *(float4*)(g_c + hu * 128 + l4);

    float4 cn, hn;
    {
        float iv = sigf(gi.x + xi.x), fv = sigf(gf.x + xf.x);
        float gv = tanhf(gg.x + xg.x), ov = sigf(go.x + xo.x);
        cn.x = fv * cv.x + iv * gv;  hn.x = ov * tanhf(cn.x);
    }
    {
        float iv = sigf(gi.y + xi.y), fv = sigf(gf.y + xf.y);
        float gv = tanhf(gg.y + xg.y), ov = sigf(go.y + xo.y);
        cn.y = fv * cv.y + iv * gv;  hn.y = ov * tanhf(cn.y);
    }
    {
        float iv = sigf(gi.z + xi.z), fv = sigf(gf.z + xf.z);
        float gv = tanhf(gg.z + xg.z), ov = sigf(go.z + xo.z);
        cn.z = fv * cv.z + iv * gv;  hn.z = ov * tanhf(cn.z);
    }
    {
        float iv = sigf(gi.w + xi.w), fv = sigf(gf.w + xf.w);
        float gv = tanhf(gg.w + xg.w), ov = sigf(go.w + xo.w);
        cn.w = fv * cv.w + iv * gv;  hn.w = ov * tanhf(cn.w);
    }
    *(float4*)(g_c + hu * 128 + l4) = cn;
    *(float4*)(g_h + hu * 128 + l4) = hn;
    *(float4*)(g_hh + ((size_t)t * 512 + hu) * 128 + l4) = hn;
}

// ---------------- K5: gather h at lengths-1, output linear + sigmoid ----------------
__global__ void k_out(const float* __restrict__ Wo, const float* __restrict__ bo,
                      const int* __restrict__ lengths, float* __restrict__ out) {
    int b = blockIdx.x, o = blockIdx.y;
    int tid = threadIdx.x;             // 128
    int t = lengths[b] - 1;
    const float* hrow = g_hh + (size_t)t * 512 * 128;
    float acc = 0.0f;
    for (int k = tid; k < 512; k += 128) {
        acc += Wo[o * 1024 + k]       * hrow[k * 128 + b];        // LSTM segment 0
        acc += Wo[o * 1024 + 512 + k] * hrow[k * 128 + 64 + b];   // LSTM segment 1
    }
    __shared__ float red[128];
    red[tid] = acc;
    __syncthreads();
    for (int s = 64; s > 0; s >>= 1) {
        if (tid < s) red[tid] += red[tid + s];
        __syncthreads();
    }
    if (tid == 0) out[b * 14 + o] = 1.0f / (1.0f + expf(-(red[0] + bo[o])));
}

// ---------------- launch ----------------
extern "C" void kernel_launch(void* const* d_in, const int* in_sizes, int n_in,
                              void* d_out, int out_size) {
    const float* x     = (const float*)d_in[0];
    const int*   len   = (const int*)  d_in[1];
    const float* h0    = (const float*)d_in[2];
    const float* c0    = (const float*)d_in[3];
    const float* Wis0  = (const float*)d_in[4];
    const float* bis0  = (const float*)d_in[5];
    const float* Wis1  = (const float*)d_in[6];
    const float* bis1  = (const float*)d_in[7];
    const float* Wih   = (const float*)d_in[8];
    const float* Whh   = (const float*)d_in[9];
    const float* bih   = (const float*)d_in[10];
    const float* bhh   = (const float*)d_in[11];
    const float* Wo    = (const float*)d_in[12];
    const float* bo    = (const float*)d_in[13];
    float* out = (float*)d_out;

    k_prep<<<2048, 128>>>(Wis0, bis0, Wis1, bis1, Wih, bih, bhh);
    k_init<<<128, 256>>>(h0, c0);
    k_temb<<<8192, 256>>>(x);
    k_gemm<<<dim3(16, 64), 256>>>(x, Wih);
    for (int t = 0; t < 128; t++) k_step<<<128, 128>>>(Whh, t);
    k_out<<<dim3(64, 14), 128>>>(Wo, bo, len, out);
}

// round 7
// speedup vs baseline: 1.0140x; 1.0140x over previous
#include <cuda_runtime.h>
#include <math.h>

// Problem constants
#define BB   64      // batch
#define TT   128     // seq len
#define HH   512     // hidden
#define NSEQ 128     // B * S (2 segments batched)
#define NBLK 128     // persistent grid size

// ---------------- scratch (__device__ globals; no allocations) ----------------
__device__ float g_temb[8192 * 1024];              // [n=b*T+t][1024] timestep embeddings
__device__ float g_gin [(size_t)128 * 2048 * 128]; // [t2][r][seq] fused input gates (+biases)
__device__ float g_hh  [(size_t)128 * 512 * 128];  // [t2][k][seq] h history
__device__ float g_h   [512 * 128];                // [k][seq] h at t=0 (init)
__device__ float g_c   [512 * 128];                // [k][seq] c init
__device__ float g_M   [14 * 2048];                // folded small-input matrices
__device__ float g_cst [2 * 2048];                 // folded constants per input-segment
__device__ unsigned int g_bar;                     // grid barrier counter

__device__ __forceinline__ float sigf(float x) { return 1.0f / (1.0f + expf(-x)); }

// ---------------- K0: fold W_is / biases into M and const ----------------
__global__ void k_prep(const float* __restrict__ Wis0, const float* __restrict__ bis0,
                       const float* __restrict__ Wis1, const float* __restrict__ bis1,
                       const float* __restrict__ Wih,  const float* __restrict__ bih,
                       const float* __restrict__ bhh) {
    int r   = blockIdx.x;          // gate row 0..2047
    int tid = threadIdx.x;         // 128
    float acc[16];
#pragma unroll
    for (int j = 0; j < 16; j++) acc[j] = 0.0f;
    const float* wr = Wih + (size_t)r * 1536;      // W_ih row r, cols 0..511 used here
    for (int k = tid; k < 512; k += 128) {
        float w = wr[k];
#pragma unroll
        for (int j = 0; j < 8; j++) acc[j]     += Wis0[k * 8 + j] * w;
#pragma unroll
        for (int j = 0; j < 6; j++) acc[8 + j] += Wis1[k * 6 + j] * w;
        acc[14] += bis0[k] * w;
        acc[15] += bis1[k] * w;
    }
    __shared__ float red[16][128];
#pragma unroll
    for (int j = 0; j < 16; j++) red[j][tid] = acc[j];
    __syncthreads();
    for (int s = 64; s > 0; s >>= 1) {
        if (tid < s) {
#pragma unroll
            for (int j = 0; j < 16; j++) red[j][tid] += red[j][tid + s];
        }
        __syncthreads();
    }
    if (tid < 14) g_M[tid * 2048 + r] = red[tid][0];
    if (tid == 14) g_cst[r]        = red[14][0] + bih[r] + bhh[r];
    if (tid == 15) g_cst[2048 + r] = red[15][0] + bih[r] + bhh[r];
}

// ---------------- K1: init h/c (both LSTM segments share h0/c0), seq-minor; reset barrier ----------------
__global__ void k_init(const float* __restrict__ h0, const float* __restrict__ c0) {
    int idx = blockIdx.x * blockDim.x + threadIdx.x;   // over 512*64
    if (idx == 0) g_bar = 0u;                          // reset grid barrier each launch/replay
    if (idx >= 512 * 64) return;
    int k = idx >> 6, b = idx & 63;
    float hv = h0[b * 512 + k], cv = c0[b * 512 + k];
    g_h[k * 128 + b]      = hv;  g_h[k * 128 + 64 + b] = hv;
    g_c[k * 128 + b]      = cv;  g_c[k * 128 + 64 + b] = cv;
}

// ---------------- K2: timestep embeddings (cos|sin for both time columns) ----------------
__global__ void k_temb(const float* __restrict__ x) {
    int n = blockIdx.x;          // 0..8191 (= b*128 + t)
    int i = threadIdx.x;         // 0..255
    float tc = x[n * 16 + 0];
    float tp = x[n * 16 + 1];
    float f  = expf(-9.210340371976184f * (float)i * (1.0f / 256.0f)); // ln(10000)
    float s, c;
    float* row = g_temb + (size_t)n * 1024;
    sincosf(tc * f, &s, &c);
    row[i]       = c;  row[256 + i] = s;
    sincosf(tp * f, &s, &c);
    row[512 + i] = c;  row[768 + i] = s;
}

// ---------------- K3: big GEMM  g_in = t_emb @ W_ih[:,512:1536].T  + small-rank epilogue ----------------
// torch reshape semantics: concat([e0,e1],dim=1) -> [B*T,2,3H] -> reshape(B,2,T,3H).
// Element (orig_t=t, input_seg=s) lands at LSTM segment s2 = t>>6, step t2 = 2*(t&63)+s.
__global__ __launch_bounds__(256, 2) void k_gemm(const float* __restrict__ x,
                                                 const float* __restrict__ Wih) {
    __shared__ float As[8][132];
    __shared__ float Bs[8][132];
    int bx = blockIdx.x;               // 0..15  (N tiles)
    int by = blockIdx.y;               // 0..63  (M tiles == batch b)
    int tid = threadIdx.x;
    int tx = tid & 15, ty = tid >> 4;  // 16x16 thread grid, 8x8 outputs each
    int lrow = tid >> 1;               // 0..127
    int lq   = (tid & 1) * 4;          // 0 or 4
    const float* Ag = g_temb + ((size_t)(by * 128 + lrow)) * 1024 + lq;
    const float* Bg = Wih    + ((size_t)(bx * 128 + lrow)) * 1536 + 512 + lq;

    float acc[8][8];
#pragma unroll
    for (int i = 0; i < 8; i++)
#pragma unroll
        for (int j = 0; j < 8; j++) acc[i][j] = 0.0f;

    for (int kt = 0; kt < 1024; kt += 8) {
        float4 a4 = *(const float4*)(Ag + kt);
        float4 b4 = *(const float4*)(Bg + kt);
        As[lq + 0][lrow] = a4.x; As[lq + 1][lrow] = a4.y;
        As[lq + 2][lrow] = a4.z; As[lq + 3][lrow] = a4.w;
        Bs[lq + 0][lrow] = b4.x; Bs[lq + 1][lrow] = b4.y;
        Bs[lq + 2][lrow] = b4.z; Bs[lq + 3][lrow] = b4.w;
        __syncthreads();
#pragma unroll
        for (int kk = 0; kk < 8; kk++) {
            float a[8], b[8];
#pragma unroll
            for (int i = 0; i < 8; i++) a[i] = As[kk][ty * 8 + i];
#pragma unroll
            for (int j = 0; j < 8; j++) b[j] = Bs[kk][tx * 8 + j];
#pragma unroll
            for (int i = 0; i < 8; i++)
#pragma unroll
                for (int j = 0; j < 8; j++) acc[i][j] += a[i] * b[j];
        }
        __syncthreads();
    }

    // Epilogue: add folded small-input term + constants; scatter per torch reshape.
#pragma unroll
    for (int i = 0; i < 8; i++) {
        int t = ty * 8 + i;                      // original timestep
        int s2 = t >> 6;                         // LSTM segment
        int t0 = 2 * (t & 63);                   // LSTM step for input-seg 0 (v1 -> t0+1)
        int seq = s2 * 64 + by;
        const float* xr = x + ((size_t)by * 128 + t) * 16 + 2;
        float xs[14];
#pragma unroll
        for (int jj = 0; jj < 14; jj++) xs[jj] = xr[jj];
#pragma unroll
        for (int j = 0; j < 8; j++) {
            int r = bx * 128 + tx * 8 + j;
            float base = acc[i][j];
            float v0 = base + g_cst[r];
            float v1 = base + g_cst[2048 + r];
#pragma unroll
            for (int jj = 0; jj < 8; jj++) v0 += xs[jj] * g_M[jj * 2048 + r];
#pragma unroll
            for (int jj = 0; jj < 6; jj++) v1 += xs[8 + jj] * g_M[(8 + jj) * 2048 + r];
            g_gin[((size_t)t0 * 2048 + r) * 128 + seq]       = v0;
            g_gin[((size_t)(t0 + 1) * 2048 + r) * 128 + seq] = v1;
        }
    }
}

// ---------------- K4: persistent LSTM recurrence. 128 resident blocks, grid-sync per step ----------------
// Block owns hidden units j4..j4+3 (all 4 gates). W_hh staged to smem ONCE. c lives in registers.
__global__ __launch_bounds__(128) void k_rnn(const float* __restrict__ Whh) {
    __shared__ float Wsm[16][512];   // rows: gr = gate*4 + u   (32 KB)
    __shared__ float gsm[16][128];   // Wh·h partials [gr][seq] (8 KB)
    int j4   = blockIdx.x * 4;       // hidden unit base
    int tid  = threadIdx.x;          // 128
    int w    = tid >> 5;             // warp == gate index 0..3
    int lane = tid & 31;
    int w4   = w * 4;

    // Stage 16 W_hh rows into smem ONCE (rows: gate*512 + j4 + u)
#pragma unroll
    for (int gr = 0; gr < 16; gr++) {
        int grow = (gr >> 2) * 512 + j4 + (gr & 3);
        *(float4*)&Wsm[gr][tid * 4] = *(const float4*)(Whh + (size_t)grow * 512 + tid * 4);
    }

    // Persistent cell state: thread (u = tid>>5) owns unit j4+u, seqs 4*lane..+3
    int u  = tid >> 5;
    int l4 = 4 * lane;
    int hu = j4 + u;
    float4 cv = *(const float4*)(g_c + hu * 128 + l4);
    __syncthreads();

    for (int t = 0; t < 128; t++) {
        const float* hsrc = (t == 0) ? g_h : (g_hh + (size_t)(t - 1) * 512 * 128);

        // gates_wh[gr][seq] = sum_k Wsm[gr][k] * h[k][seq]; lane handles seqs 4*lane..+3
        float a0[4] = {0,0,0,0}, a1[4] = {0,0,0,0}, a2[4] = {0,0,0,0}, a3[4] = {0,0,0,0};
#pragma unroll 2
        for (int k = 0; k < 512; k += 4) {
            float4 wv0 = *(const float4*)&Wsm[w4 + 0][k];
            float4 wv1 = *(const float4*)&Wsm[w4 + 1][k];
            float4 wv2 = *(const float4*)&Wsm[w4 + 2][k];
            float4 wv3 = *(const float4*)&Wsm[w4 + 3][k];
            const float* p0 = (const float*)&wv0;
            const float* p1 = (const float*)&wv1;
            const float* p2 = (const float*)&wv2;
            const float* p3 = (const float*)&wv3;
#pragma unroll
            for (int q = 0; q < 4; q++) {
                float4 hv = *(const float4*)(hsrc + (size_t)(k + q) * 128 + l4);
                float w0 = p0[q], w1 = p1[q], w2 = p2[q], w3 = p3[q];
                a0[0] += w0 * hv.x; a0[1] += w0 * hv.y; a0[2] += w0 * hv.z; a0[3] += w0 * hv.w;
                a1[0] += w1 * hv.x; a1[1] += w1 * hv.y; a1[2] += w1 * hv.z; a1[3] += w1 * hv.w;
                a2[0] += w2 * hv.x; a2[1] += w2 * hv.y; a2[2] += w2 * hv.z; a2[3] += w2 * hv.w;
                a3[0] += w3 * hv.x; a3[1] += w3 * hv.y; a3[2] += w3 * hv.z; a3[3] += w3 * hv.w;
            }
        }
        *(float4*)&gsm[w4 + 0][l4] = make_float4(a0[0], a0[1], a0[2], a0[3]);
        *(float4*)&gsm[w4 + 1][l4] = make_float4(a1[0], a1[1], a1[2], a1[3]);
        *(float4*)&gsm[w4 + 2][l4] = make_float4(a2[0], a2[1], a2[2], a2[3]);
        *(float4*)&gsm[w4 + 3][l4] = make_float4(a3[0], a3[1], a3[2], a3[3]);
        __syncthreads();

        // Update phase
        float4 gi = *(float4*)&gsm[u][l4];
        float4 gf = *(float4*)&gsm[4 + u][l4];
        float4 gg = *(float4*)&gsm[8 + u][l4];
        float4 go = *(float4*)&gsm[12 + u][l4];
        const float* ginb = g_gin + (size_t)t * 2048 * 128;
        float4 xi = *(const float4*)(ginb + ((size_t)(0    + hu)) * 128 + l4);
        float4 xf = *(const float4*)(ginb + ((size_t)(512  + hu)) * 128 + l4);
        float4 xg = *(const float4*)(ginb + ((size_t)(1024 + hu)) * 128 + l4);
        float4 xo = *(const float4*)(ginb + ((size_t)(1536 + hu)) * 128 + l4);

        float4 hn;
        {
            float iv = sigf(gi.x + xi.x), fv = sigf(gf.x + xf.x);
            float gv = tanhf(gg.x + xg.x), ov = sigf(go.x + xo.x);
            cv.x = fv * cv.x + iv * gv;  hn.x = ov * tanhf(cv.x);
        }
        {
            float iv = sigf(gi.y + xi.y), fv = sigf(gf.y + xf.y);
            float gv = tanhf(gg.y + xg.y), ov = sigf(go.y + xo.y);
            cv.y = fv * cv.y + iv * gv;  hn.y = ov * tanhf(cv.y);
        }
        {
            float iv = sigf(gi.z + xi.z), fv = sigf(gf.z + xf.z);
            float gv = tanhf(gg.z + xg.z), ov = sigf(go.z + xo.z);
            cv.z = fv * cv.z + iv * gv;  hn.z = ov * tanhf(cv.z);
        }
        {
            float iv = sigf(gi.w + xi.w), fv = sigf(gf.w + xf.w);
            float gv = tanhf(gg.w + xg.w), ov = sigf(go.w + xo.w);
            cv.w = fv * cv.w + iv * gv;  hn.w = ov * tanhf(cv.w);
        }
        *(float4*)(g_hh + ((size_t)t * 512 + hu) * 128 + l4) = hn;

        // Grid barrier (skip after the final step; kernel boundary is the fence)
        if (t < 127) {
            __syncthreads();                 // all writes of this block done; gsm safe to reuse
            if (tid == 0) {
                __threadfence();             // publish g_hh[t] writes
                atomicAdd(&g_bar, 1u);
                unsigned target = (unsigned)(t + 1) * NBLK;
                volatile unsigned int* vb = &g_bar;
                while (*vb < target) { }
            }
            __syncthreads();                 // release whole block
        }
    }
}

// ---------------- K5: gather h at lengths-1, output linear + sigmoid ----------------
__global__ void k_out(const float* __restrict__ Wo, const float* __restrict__ bo,
                      const int* __restrict__ lengths, float* __restrict__ out) {
    int b = blockIdx.x, o = blockIdx.y;
    int tid = threadIdx.x;             // 128
    int t = lengths[b] - 1;
    const float* hrow = g_hh + (size_t)t * 512 * 128;
    float acc = 0.0f;
    for (int k = tid; k < 512; k += 128) {
        acc += Wo[o * 1024 + k]       * hrow[k * 128 + b];        // LSTM segment 0
        acc += Wo[o * 1024 + 512 + k] * hrow[k * 128 + 64 + b];   // LSTM segment 1
    }
    __shared__ float red[128];
    red[tid] = acc;
    __syncthreads();
    for (int s = 64; s > 0; s >>= 1) {
        if (tid < s) red[tid] += red[tid + s];
        __syncthreads();
    }
    if (tid == 0) out[b * 14 + o] = 1.0f / (1.0f + expf(-(red[0] + bo[o])));
}

// ---------------- launch ----------------
extern "C" void kernel_launch(void* const* d_in, const int* in_sizes, int n_in,
                              void* d_out, int out_size) {
    const float* x     = (const float*)d_in[0];
    const int*   len   = (const int*)  d_in[1];
    const float* h0    = (const float*)d_in[2];
    const float* c0    = (const float*)d_in[3];
    const float* Wis0  = (const float*)d_in[4];
    const float* bis0  = (const float*)d_in[5];
    const float* Wis1  = (const float*)d_in[6];
    const float* bis1  = (const float*)d_in[7];
    const float* Wih   = (const float*)d_in[8];
    const float* Whh   = (const float*)d_in[9];
    const float* bih   = (const float*)d_in[10];
    const float* bhh   = (const float*)d_in[11];
    const float* Wo    = (const float*)d_in[12];
    const float* bo    = (const float*)d_in[13];
    float* out = (float*)d_out;

    k_prep<<<2048, 128>>>(Wis0, bis0, Wis1, bis1, Wih, bih, bhh);
    k_init<<<128, 256>>>(h0, c0);
    k_temb<<<8192, 256>>>(x);
    k_gemm<<<dim3(16, 64), 256>>>(x, Wih);
    k_rnn<<<NBLK, 128>>>(Whh);
    k_out<<<dim3(64, 14), 128>>>(Wo, bo, len, out);
}

// round 10
// speedup vs baseline: 1.3664x; 1.3475x over previous
#include <cuda_runtime.h>
#include <cuda_bf16.h>
#include <math.h>
#include <stdint.h>

// Problem constants
#define BB   64      // batch
#define TT   128     // seq len
#define HH   512     // hidden
#define NSEQ 128     // B * S (2 segments batched)
#define NBLK 128     // persistent grid size

// ---------------- scratch (__device__ globals; no allocations) ----------------
__device__ __nv_bfloat16 g_Ah[(size_t)8192 * 1024]; // t_emb hi  [n][1024]
__device__ __nv_bfloat16 g_Al[(size_t)8192 * 1024]; // t_emb lo
__device__ __nv_bfloat16 g_Bh[(size_t)2048 * 1024]; // W_ih[:,512:1536] hi [r][1024]
__device__ __nv_bfloat16 g_Bl[(size_t)2048 * 1024]; // W_ih lo
__device__ float g_gin [(size_t)128 * 128 * 2048];  // [t2][seq][r] fused input gates (+biases)
__device__ float g_hh  [(size_t)128 * 512 * 128];   // [t2][k][seq] h history
__device__ float g_h   [512 * 128];                 // [k][seq] h at t=0
__device__ float g_c   [512 * 128];                 // [k][seq] c init
__device__ float g_Mt  [2048 * 16];                 // per-gate-row: {M_e0[8], M_e1[6], cst0, cst1}
__device__ unsigned int g_bar;                      // grid barrier counter

__device__ __forceinline__ float sigf(float x) { return 1.0f / (1.0f + expf(-x)); }

__device__ __forceinline__ uint32_t smem_u32(const void* p) {
    uint32_t a;
    asm("{ .reg .u64 t; cvta.to.shared.u64 t, %1; cvt.u32.u64 %0, t; }" : "=r"(a) : "l"(p));
    return a;
}
__device__ __forceinline__ void ldsm4(uint32_t* r, uint32_t addr) {
    asm volatile("ldmatrix.sync.aligned.m8n8.x4.shared.b16 {%0,%1,%2,%3}, [%4];"
                 : "=r"(r[0]), "=r"(r[1]), "=r"(r[2]), "=r"(r[3]) : "r"(addr));
}
__device__ __forceinline__ void mma16816(float* c, const uint32_t* a, const uint32_t* b) {
    asm volatile("mma.sync.aligned.m16n8k16.row.col.f32.bf16.bf16.f32 "
                 "{%0,%1,%2,%3}, {%4,%5,%6,%7}, {%8,%9}, {%0,%1,%2,%3};"
                 : "+f"(c[0]), "+f"(c[1]), "+f"(c[2]), "+f"(c[3])
                 : "r"(a[0]), "r"(a[1]), "r"(a[2]), "r"(a[3]), "r"(b[0]), "r"(b[1]));
}

// ---------------- K0: fold W_is / biases; write g_Mt[r][16] ----------------
__global__ void k_prep(const float* __restrict__ Wis0, const float* __restrict__ bis0,
                       const float* __restrict__ Wis1, const float* __restrict__ bis1,
                       const float* __restrict__ Wih,  const float* __restrict__ bih,
                       const float* __restrict__ bhh) {
    int r   = blockIdx.x;          // gate row 0..2047
    int tid = threadIdx.x;         // 128
    float acc[16];
#pragma unroll
    for (int j = 0; j < 16; j++) acc[j] = 0.0f;
    const float* wr = Wih + (size_t)r * 1536;      // W_ih row r, cols 0..511
    for (int k = tid; k < 512; k += 128) {
        float w = wr[k];
#pragma unroll
        for (int j = 0; j < 8; j++) acc[j]     += Wis0[k * 8 + j] * w;
#pragma unroll
        for (int j = 0; j < 6; j++) acc[8 + j] += Wis1[k * 6 + j] * w;
        acc[14] += bis0[k] * w;
        acc[15] += bis1[k] * w;
    }
    __shared__ float red[16][128];
#pragma unroll
    for (int j = 0; j < 16; j++) red[j][tid] = acc[j];
    __syncthreads();
    for (int s = 64; s > 0; s >>= 1) {
        if (tid < s) {
#pragma unroll
            for (int j = 0; j < 16; j++) red[j][tid] += red[j][tid + s];
        }
        __syncthreads();
    }
    if (tid < 14) g_Mt[r * 16 + tid] = red[tid][0];
    if (tid == 14) g_Mt[r * 16 + 14] = red[14][0] + bih[r] + bhh[r];
    if (tid == 15) g_Mt[r * 16 + 15] = red[15][0] + bih[r] + bhh[r];
}

// ---------------- K1: init h/c, reset barrier ----------------
__global__ void k_init(const float* __restrict__ h0, const float* __restrict__ c0) {
    int idx = blockIdx.x * blockDim.x + threadIdx.x;
    if (idx == 0) g_bar = 0u;
    if (idx >= 512 * 64) return;
    int k = idx >> 6, b = idx & 63;
    float hv = h0[b * 512 + k], cv = c0[b * 512 + k];
    g_h[k * 128 + b]      = hv;  g_h[k * 128 + 64 + b] = hv;
    g_c[k * 128 + b]      = cv;  g_c[k * 128 + 64 + b] = cv;
}

// ---------------- K2: timestep embeddings, write bf16 hi/lo directly ----------------
__global__ void k_temb(const float* __restrict__ x) {
    int n = blockIdx.x;          // 0..8191 (= b*128 + t)
    int i = threadIdx.x;         // 0..255
    float tc = x[n * 16 + 0];
    float tp = x[n * 16 + 1];
    float f  = expf(-9.210340371976184f * (float)i * (1.0f / 256.0f));
    float s, c;
    __nv_bfloat16* ah = g_Ah + (size_t)n * 1024;
    __nv_bfloat16* al = g_Al + (size_t)n * 1024;
    sincosf(tc * f, &s, &c);
    {
        __nv_bfloat16 h = __float2bfloat16(c);
        ah[i] = h;        al[i] = __float2bfloat16(c - __bfloat162float(h));
        h = __float2bfloat16(s);
        ah[256 + i] = h;  al[256 + i] = __float2bfloat16(s - __bfloat162float(h));
    }
    sincosf(tp * f, &s, &c);
    {
        __nv_bfloat16 h = __float2bfloat16(c);
        ah[512 + i] = h;  al[512 + i] = __float2bfloat16(c - __bfloat162float(h));
        h = __float2bfloat16(s);
        ah[768 + i] = h;  al[768 + i] = __float2bfloat16(s - __bfloat162float(h));
    }
}

// ---------------- K2b: convert W_ih[:,512:1536] to bf16 hi/lo ----------------
__global__ void k_cvtw(const float* __restrict__ Wih) {
    int r = blockIdx.x;          // 0..2047
    for (int k = threadIdx.x; k < 1024; k += 256) {
        float w = Wih[(size_t)r * 1536 + 512 + k];
        __nv_bfloat16 h = __float2bfloat16(w);
        g_Bh[(size_t)r * 1024 + k] = h;
        g_Bl[(size_t)r * 1024 + k] = __float2bfloat16(w - __bfloat162float(h));
    }
}

// ---------------- K3: HMMA bf16 GEMM  gin = t_emb @ W_ih[:,512:1536].T (hi/lo split, 3 products) ----------------
// Block: 256 thr (8 warps, 2x4). Tile M=128 (temb rows of batch by), N=128 (gate rows, bx), K in chunks of 32.
// Warp computes 64x32 via m16n8k16 fragments. Smem pitch 40 bf16 (80B) -> conflict-free ldmatrix.
#define MPITCH 40
__global__ __launch_bounds__(256) void k_mma(const float* __restrict__ x) {
    __shared__ __align__(16) __nv_bfloat16 sAh[128 * MPITCH];
    __shared__ __align__(16) __nv_bfloat16 sAl[128 * MPITCH];
    __shared__ __align__(16) __nv_bfloat16 sBh[128 * MPITCH];
    __shared__ __align__(16) __nv_bfloat16 sBl[128 * MPITCH];

    int tid = threadIdx.x;
    int warp = tid >> 5, lane = tid & 31;
    int warp_m = warp >> 2;           // 0..1
    int warp_n = warp & 3;            // 0..3
    int bx = blockIdx.x;              // n-tile 0..15
    int by = blockIdx.y;              // m-tile == batch b, 0..63

    const __nv_bfloat16* srcA_h = g_Ah + (size_t)by * 128 * 1024;
    const __nv_bfloat16* srcA_l = g_Al + (size_t)by * 128 * 1024;
    const __nv_bfloat16* srcB_h = g_Bh + (size_t)bx * 128 * 1024;
    const __nv_bfloat16* srcB_l = g_Bl + (size_t)bx * 128 * 1024;

    uint32_t uAh = smem_u32(sAh), uAl = smem_u32(sAl);
    uint32_t uBh = smem_u32(sBh), uBl = smem_u32(sBl);

    int la7 = lane & 7, lb = (lane >> 3) & 1, lc = lane >> 4;
    int arow = warp_m * 64 + la7 + lb * 8;    // + mi*16
    int acol0 = lc * 8;                        // + ks*16
    int brow = warp_n * 32 + la7 + lc * 8;    // + nt*16
    int bcol0 = lb * 8;                        // + ks*16

    float acc[4][4][4];
#pragma unroll
    for (int i = 0; i < 4; i++)
#pragma unroll
        for (int j = 0; j < 4; j++)
#pragma unroll
            for (int q = 0; q < 4; q++) acc[i][j][q] = 0.0f;

    for (int kt = 0; kt < 32; kt++) {
        int kc = kt * 32;
        // load 4 buffers: 128 rows x 32 bf16 (64B/row), 512 uint4 each
#pragma unroll
        for (int rep = 0; rep < 2; rep++) {
            int i = tid + rep * 256;
            int row = i >> 2, q = i & 3;
            size_t gs = (size_t)row * 1024 + kc + q * 8;
            int ss = row * MPITCH + q * 8;
            *(uint4*)(sAh + ss) = *(const uint4*)(srcA_h + gs);
            *(uint4*)(sAl + ss) = *(const uint4*)(srcA_l + gs);
            *(uint4*)(sBh + ss) = *(const uint4*)(srcB_h + gs);
            *(uint4*)(sBl + ss) = *(const uint4*)(srcB_l + gs);
        }
        __syncthreads();

#pragma unroll
        for (int ks = 0; ks < 2; ks++) {
            uint32_t ah[4][4], al[4][4], bh[4][2], bl[4][2];
            int acol = ks * 16 + acol0;
            int bcol = ks * 16 + bcol0;
#pragma unroll
            for (int mi = 0; mi < 4; mi++) {
                uint32_t off = (uint32_t)(((arow + mi * 16) * MPITCH + acol) * 2);
                ldsm4(ah[mi], uAh + off);
                ldsm4(al[mi], uAl + off);
            }
#pragma unroll
            for (int nt = 0; nt < 2; nt++) {
                uint32_t off = (uint32_t)(((brow + nt * 16) * MPITCH + bcol) * 2);
                uint32_t r[4];
                ldsm4(r, uBh + off);
                bh[nt * 2][0] = r[0]; bh[nt * 2][1] = r[1];
                bh[nt * 2 + 1][0] = r[2]; bh[nt * 2 + 1][1] = r[3];
                ldsm4(r, uBl + off);
                bl[nt * 2][0] = r[0]; bl[nt * 2][1] = r[1];
                bl[nt * 2 + 1][0] = r[2]; bl[nt * 2 + 1][1] = r[3];
            }
#pragma unroll
            for (int mi = 0; mi < 4; mi++)
#pragma unroll
                for (int ni = 0; ni < 4; ni++) {
                    mma16816(acc[mi][ni], ah[mi], bh[ni]);
                    mma16816(acc[mi][ni], ah[mi], bl[ni]);
                    mma16816(acc[mi][ni], al[mi], bh[ni]);
                }
        }
        __syncthreads();
    }

    // Epilogue: c-fragment (row = lane>>2 (+8), cols = (lane&3)*2, +1). Add small-rank term; scatter.
    int gr = lane >> 2, gc = (lane & 3) * 2;
#pragma unroll
    for (int mi = 0; mi < 4; mi++) {
#pragma unroll
        for (int half = 0; half < 2; half++) {
            int m = warp_m * 64 + mi * 16 + gr + half * 8;   // original timestep t
            int s2 = m >> 6;
            int t0 = 2 * (m & 63);
            int seq = s2 * 64 + by;
            const float* xr = x + ((size_t)(by * 128 + m)) * 16 + 2;
            float xs[14];
#pragma unroll
            for (int jj = 0; jj < 14; jj++) xs[jj] = xr[jj];
            float* g0 = g_gin + ((size_t)t0 * 128 + seq) * 2048 + bx * 128;
            float* g1 = g0 + (size_t)128 * 2048;
#pragma unroll
            for (int ni = 0; ni < 4; ni++) {
                int lcol = warp_n * 32 + ni * 8 + gc;        // local col in 128
                int r = bx * 128 + lcol;
                float b0 = acc[mi][ni][half * 2 + 0];
                float b1 = acc[mi][ni][half * 2 + 1];
                float v0a, v1a, v0b, v1b;
                {
                    const float4* mt = (const float4*)(g_Mt + (size_t)r * 16);
                    float4 m0 = mt[0], m1 = mt[1], m2 = mt[2], m3 = mt[3];
                    v0a = b0 + m3.z + xs[0]*m0.x + xs[1]*m0.y + xs[2]*m0.z + xs[3]*m0.w
                               + xs[4]*m1.x + xs[5]*m1.y + xs[6]*m1.z + xs[7]*m1.w;
                    v1a = b0 + m3.w + xs[8]*m2.x + xs[9]*m2.y + xs[10]*m2.z + xs[11]*m2.w
                               + xs[12]*m3.x + xs[13]*m3.y;
                }
                {
                    const float4* mt = (const float4*)(g_Mt + (size_t)(r + 1) * 16);
                    float4 m0 = mt[0], m1 = mt[1], m2 = mt[2], m3 = mt[3];
                    v0b = b1 + m3.z + xs[0]*m0.x + xs[1]*m0.y + xs[2]*m0.z + xs[3]*m0.w
                               + xs[4]*m1.x + xs[5]*m1.y + xs[6]*m1.z + xs[7]*m1.w;
                    v1b = b1 + m3.w + xs[8]*m2.x + xs[9]*m2.y + xs[10]*m2.z + xs[11]*m2.w
                               + xs[12]*m3.x + xs[13]*m3.y;
                }
                *(float2*)(g0 + lcol) = make_float2(v0a, v0b);
                *(float2*)(g1 + lcol) = make_float2(v1a, v1b);
            }
        }
    }
}

// ---------------- K4: persistent LSTM recurrence. 128 blocks x 256 threads, grid-sync per step ----------------
// Block owns hidden units j4..j4+3 (16 gate rows). 8 warps: gate g = w&3, k-half = w>>2.
__global__ __launch_bounds__(256) void k_rnn(const float* __restrict__ Whh) {
    __shared__ float Wsm[16][512];       // 32 KB
    __shared__ float gsm[2][16][128];    // 16 KB partials per k-half
    int j4   = blockIdx.x * 4;
    int tid  = threadIdx.x;              // 256
    int w    = tid >> 5;
    int lane = tid & 31;
    int g    = w & 3;
    int half = w >> 2;
    int w4   = g * 4;
    int k0   = half * 256;
    int l4   = 4 * lane;

    // Stage 16 W_hh rows into smem once
    for (int i = tid; i < 16 * 128; i += 256) {
        int grr = i >> 7, c4 = i & 127;
        int grow = (grr >> 2) * 512 + j4 + (grr & 3);
        *(float4*)&Wsm[grr][c4 * 4] = *(const float4*)(Whh + (size_t)grow * 512 + c4 * 4);
    }

    // Update-phase ownership: seq = tid&127, unit pair uh = tid>>7 -> units {2uh, 2uh+1}
    int useq = tid & 127;
    int uh   = tid >> 7;
    int u0   = 2 * uh;
    float c_0 = g_c[(j4 + u0)     * 128 + useq];
    float c_1 = g_c[(j4 + u0 + 1) * 128 + useq];
    __syncthreads();

    for (int t = 0; t < 128; t++) {
        const float* hsrc = (t == 0) ? g_h : (g_hh + (size_t)(t - 1) * 512 * 128);

        float a0[4] = {0,0,0,0}, a1[4] = {0,0,0,0}, a2[4] = {0,0,0,0}, a3[4] = {0,0,0,0};
#pragma unroll 2
        for (int k = k0; k < k0 + 256; k += 4) {
            float4 wv0 = *(const float4*)&Wsm[w4 + 0][k];
            float4 wv1 = *(const float4*)&Wsm[w4 + 1][k];
            float4 wv2 = *(const float4*)&Wsm[w4 + 2][k];
            float4 wv3 = *(const float4*)&Wsm[w4 + 3][k];
            const float* p0 = (const float*)&wv0;
            const float* p1 = (const float*)&wv1;
            const float* p2 = (const float*)&wv2;
            const float* p3 = (const float*)&wv3;
#pragma unroll
            for (int q = 0; q < 4; q++) {
                float4 hv = *(const float4*)(hsrc + (size_t)(k + q) * 128 + l4);
                float w0 = p0[q], w1 = p1[q], w2 = p2[q], w3 = p3[q];
                a0[0] += w0 * hv.x; a0[1] += w0 * hv.y; a0[2] += w0 * hv.z; a0[3] += w0 * hv.w;
                a1[0] += w1 * hv.x; a1[1] += w1 * hv.y; a1[2] += w1 * hv.z; a1[3] += w1 * hv.w;
                a2[0] += w2 * hv.x; a2[1] += w2 * hv.y; a2[2] += w2 * hv.z; a2[3] += w2 * hv.w;
                a3[0] += w3 * hv.x; a3[1] += w3 * hv.y; a3[2] += w3 * hv.z; a3[3] += w3 * hv.w;
            }
        }
        *(float4*)&gsm[half][w4 + 0][l4] = make_float4(a0[0], a0[1], a0[2], a0[3]);
        *(float4*)&gsm[half][w4 + 1][l4] = make_float4(a1[0], a1[1], a1[2], a1[3]);
        *(float4*)&gsm[half][w4 + 2][l4] = make_float4(a2[0], a2[1], a2[2], a2[3]);
        *(float4*)&gsm[half][w4 + 3][l4] = make_float4(a3[0], a3[1], a3[2], a3[3]);
        __syncthreads();

        // Update: thread handles (seq=useq, units u0,u0+1), gin layout [t][seq][r]
        const float* ginb = g_gin + ((size_t)t * 128 + useq) * 2048 + j4 + u0;
        float2 xi = *(const float2*)(ginb + 0);
        float2 xf = *(const float2*)(ginb + 512);
        float2 xg = *(const float2*)(ginb + 1024);
        float2 xo = *(const float2*)(ginb + 1536);

        float gi0 = gsm[0][0*4 + u0][useq] + gsm[1][0*4 + u0][useq] + xi.x;
        float gf0 = gsm[0][1*4 + u0][useq] + gsm[1][1*4 + u0][useq] + xf.x;
        float gg0 = gsm[0][2*4 + u0][useq] + gsm[1][2*4 + u0][useq] + xg.x;
        float go0 = gsm[0][3*4 + u0][useq] + gsm[1][3*4 + u0][useq] + xo.x;
        float gi1 = gsm[0][0*4 + u0+1][useq] + gsm[1][0*4 + u0+1][useq] + xi.y;
        float gf1 = gsm[0][1*4 + u0+1][useq] + gsm[1][1*4 + u0+1][useq] + xf.y;
        float gg1 = gsm[0][2*4 + u0+1][useq] + gsm[1][2*4 + u0+1][useq] + xg.y;
        float go1 = gsm[0][3*4 + u0+1][useq] + gsm[1][3*4 + u0+1][useq] + xo.y;

        c_0 = sigf(gf0) * c_0 + sigf(gi0) * tanhf(gg0);
        float h_0 = sigf(go0) * tanhf(c_0);
        c_1 = sigf(gf1) * c_1 + sigf(gi1) * tanhf(gg1);
        float h_1 = sigf(go1) * tanhf(c_1);

        float* hdst = g_hh + (size_t)t * 512 * 128;
        hdst[(j4 + u0)     * 128 + useq] = h_0;
        hdst[(j4 + u0 + 1) * 128 + useq] = h_1;

        if (t < 127) {
            __syncthreads();
            if (tid == 0) {
                __threadfence();
                atomicAdd(&g_bar, 1u);
                unsigned target = (unsigned)(t + 1) * NBLK;
                volatile unsigned int* vb = &g_bar;
                while (*vb < target) { }
            }
            __syncthreads();
        }
    }
}

// ---------------- K5: gather h at lengths-1, output linear + sigmoid ----------------
__global__ void k_out(const float* __restrict__ Wo, const float* __restrict__ bo,
                      const int* __restrict__ lengths, float* __restrict__ out) {
    int b = blockIdx.x, o = blockIdx.y;
    int tid = threadIdx.x;             // 128
    int t = lengths[b] - 1;
    const float* hrow = g_hh + (size_t)t * 512 * 128;
    float acc = 0.0f;
    for (int k = tid; k < 512; k += 128) {
        acc += Wo[o * 1024 + k]       * hrow[k * 128 + b];        // LSTM segment 0
        acc += Wo[o * 1024 + 512 + k] * hrow[k * 128 + 64 + b];   // LSTM segment 1
    }
    __shared__ float red[128];
    red[tid] = acc;
    __syncthreads();
    for (int s = 64; s > 0; s >>= 1) {
        if (tid < s) red[tid] += red[tid + s];
        __syncthreads();
    }
    if (tid == 0) out[b * 14 + o] = 1.0f / (1.0f + expf(-(red[0] + bo[o])));
}

// ---------------- launch ----------------
extern "C" void kernel_launch(void* const* d_in, const int* in_sizes, int n_in,
                              void* d_out, int out_size) {
    const float* x     = (const float*)d_in[0];
    const int*   len   = (const int*)  d_in[1];
    const float* h0    = (const float*)d_in[2];
    const float* c0    = (const float*)d_in[3];
    const float* Wis0  = (const float*)d_in[4];
    const float* bis0  = (const float*)d_in[5];
    const float* Wis1  = (const float*)d_in[6];
    const float* bis1  = (const float*)d_in[7];
    const float* Wih   = (const float*)d_in[8];
    const float* Whh   = (const float*)d_in[9];
    const float* bih   = (const float*)d_in[10];
    const float* bhh   = (const float*)d_in[11];
    const float* Wo    = (const float*)d_in[12];
    const float* bo    = (const float*)d_in[13];
    float* out = (float*)d_out;

    k_prep<<<2048, 128>>>(Wis0, bis0, Wis1, bis1, Wih, bih, bhh);
    k_init<<<128, 256>>>(h0, c0);
    k_temb<<<8192, 256>>>(x);
    k_cvtw<<<2048, 256>>>(Wih);
    k_mma<<<dim3(16, 64), 256>>>(x);
    k_rnn<<<NBLK, 256>>>(Whh);
    k_out<<<dim3(64, 14), 128>>>(Wo, bo, len, out);
}

// round 11
// speedup vs baseline: 1.6322x; 1.1945x over previous
#include <cuda_runtime.h>
#include <cuda_bf16.h>
#include <math.h>
#include <stdint.h>

// Problem constants
#define BB   64      // batch
#define TT   128     // seq len
#define HH   512     // hidden
#define NSEQ 128     // B * S (2 segments batched)
#define RNN_BLOCKS 64

// ---------------- scratch (__device__ globals; no allocations) ----------------
__device__ __nv_bfloat16 g_Ah[(size_t)8192 * 1024]; // t_emb hi  [n][1024]
__device__ __nv_bfloat16 g_Al[(size_t)8192 * 1024]; // t_emb lo
__device__ __nv_bfloat16 g_Bh[(size_t)2048 * 1024]; // W_ih[:,512:1536] hi [r][1024]
__device__ __nv_bfloat16 g_Bl[(size_t)2048 * 1024]; // W_ih lo
__device__ float g_gin [(size_t)128 * 128 * 2048];  // [t2][seq][r] fused input gates (+biases)
__device__ __nv_bfloat16 g_hhh[(size_t)128 * 128 * 512]; // [t][seq][k] h history hi
__device__ __nv_bfloat16 g_hhl[(size_t)128 * 128 * 512]; // [t][seq][k] h history lo
__device__ __nv_bfloat16 g_h0h[128 * 512];          // [seq][k] init h hi
__device__ __nv_bfloat16 g_h0l[128 * 512];          // [seq][k] init h lo
__device__ float g_c   [512 * 128];                 // [k][seq] c init
__device__ float g_Mt  [2048 * 16];                 // per-gate-row: {M_e0[8], M_e1[6], cst0, cst1}
__device__ unsigned int g_bar;                      // grid barrier counter

__device__ __forceinline__ float sigf(float x) { return 1.0f / (1.0f + expf(-x)); }

__device__ __forceinline__ uint32_t smem_u32(const void* p) {
    uint32_t a;
    asm("{ .reg .u64 t; cvta.to.shared.u64 t, %1; cvt.u32.u64 %0, t; }" : "=r"(a) : "l"(p));
    return a;
}
__device__ __forceinline__ void ldsm4(uint32_t* r, uint32_t addr) {
    asm volatile("ldmatrix.sync.aligned.m8n8.x4.shared.b16 {%0,%1,%2,%3}, [%4];"
                 : "=r"(r[0]), "=r"(r[1]), "=r"(r[2]), "=r"(r[3]) : "r"(addr));
}
__device__ __forceinline__ void mma16816(float* c, const uint32_t* a, const uint32_t* b) {
    asm volatile("mma.sync.aligned.m16n8k16.row.col.f32.bf16.bf16.f32 "
                 "{%0,%1,%2,%3}, {%4,%5,%6,%7}, {%8,%9}, {%0,%1,%2,%3};"
                 : "+f"(c[0]), "+f"(c[1]), "+f"(c[2]), "+f"(c[3])
                 : "r"(a[0]), "r"(a[1]), "r"(a[2]), "r"(a[3]), "r"(b[0]), "r"(b[1]));
}
#define CP_ASYNC16(dst, src) \
    asm volatile("cp.async.cg.shared.global [%0], [%1], 16;" :: "r"(dst), "l"(src))

// ---------------- K0: fold W_is / biases; write g_Mt[r][16] ----------------
__global__ void k_prep(const float* __restrict__ Wis0, const float* __restrict__ bis0,
                       const float* __restrict__ Wis1, const float* __restrict__ bis1,
                       const float* __restrict__ Wih,  const float* __restrict__ bih,
                       const float* __restrict__ bhh) {
    int r   = blockIdx.x;          // gate row 0..2047
    int tid = threadIdx.x;         // 128
    float acc[16];
#pragma unroll
    for (int j = 0; j < 16; j++) acc[j] = 0.0f;
    const float* wr = Wih + (size_t)r * 1536;      // W_ih row r, cols 0..511
    for (int k = tid; k < 512; k += 128) {
        float w = wr[k];
#pragma unroll
        for (int j = 0; j < 8; j++) acc[j]     += Wis0[k * 8 + j] * w;
#pragma unroll
        for (int j = 0; j < 6; j++) acc[8 + j] += Wis1[k * 6 + j] * w;
        acc[14] += bis0[k] * w;
        acc[15] += bis1[k] * w;
    }
    __shared__ float red[16][128];
#pragma unroll
    for (int j = 0; j < 16; j++) red[j][tid] = acc[j];
    __syncthreads();
    for (int s = 64; s > 0; s >>= 1) {
        if (tid < s) {
#pragma unroll
            for (int j = 0; j < 16; j++) red[j][tid] += red[j][tid + s];
        }
        __syncthreads();
    }
    if (tid < 14) g_Mt[r * 16 + tid] = red[tid][0];
    if (tid == 14) g_Mt[r * 16 + 14] = red[14][0] + bih[r] + bhh[r];
    if (tid == 15) g_Mt[r * 16 + 15] = red[15][0] + bih[r] + bhh[r];
}

// ---------------- K1: init h (bf16 hi/lo, [seq][k]) and c (fp32 [k][seq]); reset barrier ----------------
__global__ void k_init(const float* __restrict__ h0, const float* __restrict__ c0) {
    int idx = blockIdx.x * blockDim.x + threadIdx.x;   // over 64*512
    if (idx == 0) g_bar = 0u;
    if (idx >= 64 * 512) return;
    int b = idx >> 9, k = idx & 511;
    float hv = h0[b * 512 + k], cv = c0[b * 512 + k];
    __nv_bfloat16 hi = __float2bfloat16(hv);
    __nv_bfloat16 lo = __float2bfloat16(hv - __bfloat162float(hi));
    g_h0h[(size_t)b * 512 + k] = hi;  g_h0h[(size_t)(64 + b) * 512 + k] = hi;
    g_h0l[(size_t)b * 512 + k] = lo;  g_h0l[(size_t)(64 + b) * 512 + k] = lo;
    g_c[k * 128 + b] = cv;  g_c[k * 128 + 64 + b] = cv;
}

// ---------------- K2: timestep embeddings, write bf16 hi/lo directly ----------------
__global__ void k_temb(const float* __restrict__ x) {
    int n = blockIdx.x;          // 0..8191 (= b*128 + t)
    int i = threadIdx.x;         // 0..255
    float tc = x[n * 16 + 0];
    float tp = x[n * 16 + 1];
    float f  = expf(-9.210340371976184f * (float)i * (1.0f / 256.0f));
    float s, c;
    __nv_bfloat16* ah = g_Ah + (size_t)n * 1024;
    __nv_bfloat16* al = g_Al + (size_t)n * 1024;
    sincosf(tc * f, &s, &c);
    {
        __nv_bfloat16 h = __float2bfloat16(c);
        ah[i] = h;        al[i] = __float2bfloat16(c - __bfloat162float(h));
        h = __float2bfloat16(s);
        ah[256 + i] = h;  al[256 + i] = __float2bfloat16(s - __bfloat162float(h));
    }
    sincosf(tp * f, &s, &c);
    {
        __nv_bfloat16 h = __float2bfloat16(c);
        ah[512 + i] = h;  al[512 + i] = __float2bfloat16(c - __bfloat162float(h));
        h = __float2bfloat16(s);
        ah[768 + i] = h;  al[768 + i] = __float2bfloat16(s - __bfloat162float(h));
    }
}

// ---------------- K2b: convert W_ih[:,512:1536] to bf16 hi/lo ----------------
__global__ void k_cvtw(const float* __restrict__ Wih) {
    int r = blockIdx.x;          // 0..2047
    for (int k = threadIdx.x; k < 1024; k += 256) {
        float w = Wih[(size_t)r * 1536 + 512 + k];
        __nv_bfloat16 h = __float2bfloat16(w);
        g_Bh[(size_t)r * 1024 + k] = h;
        g_Bl[(size_t)r * 1024 + k] = __float2bfloat16(w - __bfloat162float(h));
    }
}

// ---------------- K3: HMMA bf16 GEMM  gin = t_emb @ W_ih[:,512:1536].T (hi/lo split, 3 products) ----------------
#define MPITCH 40
__global__ __launch_bounds__(256) void k_mma(const float* __restrict__ x) {
    __shared__ __align__(16) __nv_bfloat16 sAh[128 * MPITCH];
    __shared__ __align__(16) __nv_bfloat16 sAl[128 * MPITCH];
    __shared__ __align__(16) __nv_bfloat16 sBh[128 * MPITCH];
    __shared__ __align__(16) __nv_bfloat16 sBl[128 * MPITCH];

    int tid = threadIdx.x;
    int warp = tid >> 5, lane = tid & 31;
    int warp_m = warp >> 2;           // 0..1
    int warp_n = warp & 3;            // 0..3
    int bx = blockIdx.x;              // n-tile 0..15
    int by = blockIdx.y;              // m-tile == batch b, 0..63

    const __nv_bfloat16* srcA_h = g_Ah + (size_t)by * 128 * 1024;
    const __nv_bfloat16* srcA_l = g_Al + (size_t)by * 128 * 1024;
    const __nv_bfloat16* srcB_h = g_Bh + (size_t)bx * 128 * 1024;
    const __nv_bfloat16* srcB_l = g_Bl + (size_t)bx * 128 * 1024;

    uint32_t uAh = smem_u32(sAh), uAl = smem_u32(sAl);
    uint32_t uBh = smem_u32(sBh), uBl = smem_u32(sBl);

    int la7 = lane & 7, lb = (lane >> 3) & 1, lc = lane >> 4;
    int arow = warp_m * 64 + la7 + lb * 8;
    int acol0 = lc * 8;
    int brow = warp_n * 32 + la7 + lc * 8;
    int bcol0 = lb * 8;

    float acc[4][4][4];
#pragma unroll
    for (int i = 0; i < 4; i++)
#pragma unroll
        for (int j = 0; j < 4; j++)
#pragma unroll
            for (int q = 0; q < 4; q++) acc[i][j][q] = 0.0f;

    for (int kt = 0; kt < 32; kt++) {
        int kc = kt * 32;
#pragma unroll
        for (int rep = 0; rep < 2; rep++) {
            int i = tid + rep * 256;
            int row = i >> 2, q = i & 3;
            size_t gs = (size_t)row * 1024 + kc + q * 8;
            int ss = row * MPITCH + q * 8;
            *(uint4*)(sAh + ss) = *(const uint4*)(srcA_h + gs);
            *(uint4*)(sAl + ss) = *(const uint4*)(srcA_l + gs);
            *(uint4*)(sBh + ss) = *(const uint4*)(srcB_h + gs);
            *(uint4*)(sBl + ss) = *(const uint4*)(srcB_l + gs);
        }
        __syncthreads();

#pragma unroll
        for (int ks = 0; ks < 2; ks++) {
            uint32_t ah[4][4], al[4][4], bh[4][2], bl[4][2];
            int acol = ks * 16 + acol0;
            int bcol = ks * 16 + bcol0;
#pragma unroll
            for (int mi = 0; mi < 4; mi++) {
                uint32_t off = (uint32_t)(((arow + mi * 16) * MPITCH + acol) * 2);
                ldsm4(ah[mi], uAh + off);
                ldsm4(al[mi], uAl + off);
            }
#pragma unroll
            for (int nt = 0; nt < 2; nt++) {
                uint32_t off = (uint32_t)(((brow + nt * 16) * MPITCH + bcol) * 2);
                uint32_t r[4];
                ldsm4(r, uBh + off);
                bh[nt * 2][0] = r[0]; bh[nt * 2][1] = r[1];
                bh[nt * 2 + 1][0] = r[2]; bh[nt * 2 + 1][1] = r[3];
                ldsm4(r, uBl + off);
                bl[nt * 2][0] = r[0]; bl[nt * 2][1] = r[1];
                bl[nt * 2 + 1][0] = r[2]; bl[nt * 2 + 1][1] = r[3];
            }
#pragma unroll
            for (int mi = 0; mi < 4; mi++)
#pragma unroll
                for (int ni = 0; ni < 4; ni++) {
                    mma16816(acc[mi][ni], ah[mi], bh[ni]);
                    mma16816(acc[mi][ni], ah[mi], bl[ni]);
                    mma16816(acc[mi][ni], al[mi], bh[ni]);
                }
        }
        __syncthreads();
    }

    int gr = lane >> 2, gc = (lane & 3) * 2;
#pragma unroll
    for (int mi = 0; mi < 4; mi++) {
#pragma unroll
        for (int half = 0; half < 2; half++) {
            int m = warp_m * 64 + mi * 16 + gr + half * 8;   // original timestep t
            int s2 = m >> 6;
            int t0 = 2 * (m & 63);
            int seq = s2 * 64 + by;
            const float* xr = x + ((size_t)(by * 128 + m)) * 16 + 2;
            float xs[14];
#pragma unroll
            for (int jj = 0; jj < 14; jj++) xs[jj] = xr[jj];
            float* g0 = g_gin + ((size_t)t0 * 128 + seq) * 2048 + bx * 128;
            float* g1 = g0 + (size_t)128 * 2048;
#pragma unroll
            for (int ni = 0; ni < 4; ni++) {
                int lcol = warp_n * 32 + ni * 8 + gc;
                int r = bx * 128 + lcol;
                float b0 = acc[mi][ni][half * 2 + 0];
                float b1 = acc[mi][ni][half * 2 + 1];
                float v0a, v1a, v0b, v1b;
                {
                    const float4* mt = (const float4*)(g_Mt + (size_t)r * 16);
                    float4 m0 = mt[0], m1 = mt[1], m2 = mt[2], m3 = mt[3];
                    v0a = b0 + m3.z + xs[0]*m0.x + xs[1]*m0.y + xs[2]*m0.z + xs[3]*m0.w
                               + xs[4]*m1.x + xs[5]*m1.y + xs[6]*m1.z + xs[7]*m1.w;
                    v1a = b0 + m3.w + xs[8]*m2.x + xs[9]*m2.y + xs[10]*m2.z + xs[11]*m2.w
                               + xs[12]*m3.x + xs[13]*m3.y;
                }
                {
                    const float4* mt = (const float4*)(g_Mt + (size_t)(r + 1) * 16);
                    float4 m0 = mt[0], m1 = mt[1], m2 = mt[2], m3 = mt[3];
                    v0b = b1 + m3.z + xs[0]*m0.x + xs[1]*m0.y + xs[2]*m0.z + xs[3]*m0.w
                               + xs[4]*m1.x + xs[5]*m1.y + xs[6]*m1.z + xs[7]*m1.w;
                    v1b = b1 + m3.w + xs[8]*m2.x + xs[9]*m2.y + xs[10]*m2.z + xs[11]*m2.w
                               + xs[12]*m3.x + xs[13]*m3.y;
                }
                *(float2*)(g0 + lcol) = make_float2(v0a, v0b);
                *(float2*)(g1 + lcol) = make_float2(v1a, v1b);
            }
        }
    }
}

// ---------------- K4: persistent HMMA LSTM recurrence ----------------
// 64 blocks x 256 thr. Block owns 8 hidden units = 32 gate rows (a = g*8+u).
// A = W_hh rows bf16 hi/lo in smem (static). B = h bf16 hi/lo streamed per step
// via double-buffered cp.async. 3-product split: Ah*Bh + Ah*Bl + Al*Bh.
#define AP 520                          // A smem pitch (bf16 elems)
#define BP 136                          // B smem pitch (bf16 elems)
#define GP 136                          // gsm pitch (floats)
#define SA_H 0
#define SA_L 33280
#define SB_H0 66560
#define SB_L0 101376
#define SB_H1 136192
#define SB_L1 171008
#define SGM   205824
#define RNN_SMEM 223232

__global__ __launch_bounds__(256) void k_rnn(const float* __restrict__ Whh) {
    extern __shared__ char sm[];
    uint32_t sb = smem_u32(sm);
    __nv_bfloat16* sAh = (__nv_bfloat16*)(sm + SA_H);
    __nv_bfloat16* sAl = (__nv_bfloat16*)(sm + SA_L);
    float* gsm = (float*)(sm + SGM);

    int tid = threadIdx.x, warp = tid >> 5, lane = tid & 31;
    int warp_m = warp >> 2, warp_n = warp & 3;
    int j8 = blockIdx.x * 8;

    // Stage A: 32 W_hh rows (a = g*8+u -> row g*512 + j8 + u) as bf16 hi/lo, once.
    for (int i = tid; i < 32 * 512; i += 256) {
        int a = i >> 9, k = i & 511;
        float w = Whh[(size_t)((a >> 3) * 512 + j8 + (a & 7)) * 512 + k];
        __nv_bfloat16 hi = __float2bfloat16(w);
        sAh[a * AP + k] = hi;
        sAl[a * AP + k] = __float2bfloat16(w - __bfloat162float(hi));
    }

    // Cell-state ownership: (units j8+u0..+3, seq useq)
    int useq = tid & 127, upair = tid >> 7;
    int u0 = upair * 4;
    float cc[4];
#pragma unroll
    for (int q = 0; q < 4; q++) cc[q] = g_c[(j8 + u0 + q) * 128 + useq];
    __syncthreads();

    int la7 = lane & 7, lb2 = (lane >> 3) & 1, lc2 = lane >> 4;
    int arow = warp_m * 16 + la7 + lb2 * 8;
    int acol0 = lc2 * 8;
    int brow = warp_n * 32 + la7 + lc2 * 8;
    int bcol0 = lb2 * 8;
    uint32_t bufH[2] = {sb + SB_H0, sb + SB_H1};
    uint32_t bufL[2] = {sb + SB_L0, sb + SB_L1};

#define ISSUE_CHUNK(KC, BUF) do {                                              \
    _Pragma("unroll")                                                          \
    for (int j = 0; j < 8; j++) {                                              \
        int gidx = tid * 8 + j;                                                \
        int row = gidx >> 4, seg = gidx & 15;                                  \
        uint32_t so = (uint32_t)(row * (BP * 2) + seg * 16);                   \
        size_t go_ = (size_t)row * 512 + (size_t)(KC) * 128 + seg * 8;         \
        CP_ASYNC16(bufH[BUF] + so, srcH + go_);                                \
        CP_ASYNC16(bufL[BUF] + so, srcL + go_);                                \
    }                                                                          \
    asm volatile("cp.async.commit_group;");                                    \
} while (0)

    for (int t = 0; t < 128; t++) {
        const __nv_bfloat16* srcH = (t == 0) ? g_h0h : (g_hhh + (size_t)(t - 1) * 65536);
        const __nv_bfloat16* srcL = (t == 0) ? g_h0l : (g_hhl + (size_t)(t - 1) * 65536);

        ISSUE_CHUNK(0, 0);

        float acc[4][4];
#pragma unroll
        for (int i = 0; i < 4; i++)
#pragma unroll
            for (int q = 0; q < 4; q++) acc[i][q] = 0.0f;

        for (int kc4 = 0; kc4 < 4; kc4++) {
            int cb = kc4 & 1;
            if (kc4 < 3) {
                ISSUE_CHUNK(kc4 + 1, cb ^ 1);
                asm volatile("cp.async.wait_group 1;");
            } else {
                asm volatile("cp.async.wait_group 0;");
            }
            __syncthreads();
#pragma unroll
            for (int ks = 0; ks < 8; ks++) {
                int acol = kc4 * 128 + ks * 16 + acol0;
                uint32_t aoff = (uint32_t)((arow * AP + acol) * 2);
                uint32_t ah[4], al[4];
                ldsm4(ah, sb + SA_H + aoff);
                ldsm4(al, sb + SA_L + aoff);
                uint32_t bh[4][2], bl[4][2];
#pragma unroll
                for (int nt = 0; nt < 2; nt++) {
                    uint32_t boff = (uint32_t)(((brow + nt * 16) * BP + bcol0 + ks * 16) * 2);
                    uint32_t r[4];
                    ldsm4(r, bufH[cb] + boff);
                    bh[nt * 2][0] = r[0]; bh[nt * 2][1] = r[1];
                    bh[nt * 2 + 1][0] = r[2]; bh[nt * 2 + 1][1] = r[3];
                    ldsm4(r, bufL[cb] + boff);
                    bl[nt * 2][0] = r[0]; bl[nt * 2][1] = r[1];
                    bl[nt * 2 + 1][0] = r[2]; bl[nt * 2 + 1][1] = r[3];
                }
#pragma unroll
                for (int ni = 0; ni < 4; ni++) {
                    mma16816(acc[ni], ah, bh[ni]);
                    mma16816(acc[ni], ah, bl[ni]);
                    mma16816(acc[ni], al, bh[ni]);
                }
            }
            __syncthreads();
        }

        // Store gate sums to gsm[a][seq]
        int r0 = warp_m * 16 + (lane >> 2);
        int c0 = warp_n * 32 + (lane & 3) * 2;
#pragma unroll
        for (int ni = 0; ni < 4; ni++) {
            *(float2*)&gsm[r0 * GP + c0 + ni * 8]       = make_float2(acc[ni][0], acc[ni][1]);
            *(float2*)&gsm[(r0 + 8) * GP + c0 + ni * 8] = make_float2(acc[ni][2], acc[ni][3]);
        }
        __syncthreads();

        // Update phase
        const float* ginb = g_gin + ((size_t)t * 128 + useq) * 2048 + j8 + u0;
        float4 xi = *(const float4*)(ginb);
        float4 xf = *(const float4*)(ginb + 512);
        float4 xg = *(const float4*)(ginb + 1024);
        float4 xo = *(const float4*)(ginb + 1536);
        float xiv[4] = {xi.x, xi.y, xi.z, xi.w};
        float xfv[4] = {xf.x, xf.y, xf.z, xf.w};
        float xgv[4] = {xg.x, xg.y, xg.z, xg.w};
        float xov[4] = {xo.x, xo.y, xo.z, xo.w};
        float hn[4];
#pragma unroll
        for (int q = 0; q < 4; q++) {
            int u = u0 + q;
            float gi = gsm[u * GP + useq]        + xiv[q];
            float gf = gsm[(8 + u) * GP + useq]  + xfv[q];
            float gg = gsm[(16 + u) * GP + useq] + xgv[q];
            float go = gsm[(24 + u) * GP + useq] + xov[q];
            cc[q] = sigf(gf) * cc[q] + sigf(gi) * tanhf(gg);
            hn[q] = sigf(go) * tanhf(cc[q]);
        }
        __align__(8) __nv_bfloat16 hhv[4], hlv[4];
#pragma unroll
        for (int q = 0; q < 4; q++) {
            __nv_bfloat16 hi = __float2bfloat16(hn[q]);
            hhv[q] = hi;
            hlv[q] = __float2bfloat16(hn[q] - __bfloat162float(hi));
        }
        size_t hb = ((size_t)t * 128 + useq) * 512 + j8 + u0;
        *(uint2*)(g_hhh + hb) = *(uint2*)hhv;
        *(uint2*)(g_hhl + hb) = *(uint2*)hlv;

        if (t < 127) {
            __syncthreads();
            if (tid == 0) {
                __threadfence();
                atomicAdd(&g_bar, 1u);
                unsigned target = (unsigned)(t + 1) * RNN_BLOCKS;
                volatile unsigned int* vb = &g_bar;
                while (*vb < target) { }
            }
            __syncthreads();
        }
    }
#undef ISSUE_CHUNK
}

// ---------------- K5: gather h at lengths-1 (hi+lo), output linear + sigmoid ----------------
__global__ void k_out(const float* __restrict__ Wo, const float* __restrict__ bo,
                      const int* __restrict__ lengths, float* __restrict__ out) {
    int b = blockIdx.x, o = blockIdx.y;
    int tid = threadIdx.x;             // 128
    int t = lengths[b] - 1;
    const __nv_bfloat16* ph = g_hhh + (size_t)t * 65536;
    const __nv_bfloat16* pl = g_hhl + (size_t)t * 65536;
    float acc = 0.0f;
    for (int k = tid; k < 512; k += 128) {
        float h0v = __bfloat162float(ph[(size_t)b * 512 + k])
                  + __bfloat162float(pl[(size_t)b * 512 + k]);
        float h1v = __bfloat162float(ph[(size_t)(64 + b) * 512 + k])
                  + __bfloat162float(pl[(size_t)(64 + b) * 512 + k]);
        acc += Wo[o * 1024 + k] * h0v + Wo[o * 1024 + 512 + k] * h1v;
    }
    __shared__ float red[128];
    red[tid] = acc;
    __syncthreads();
    for (int s = 64; s > 0; s >>= 1) {
        if (tid < s) red[tid] += red[tid + s];
        __syncthreads();
    }
    if (tid == 0) out[b * 14 + o] = 1.0f / (1.0f + expf(-(red[0] + bo[o])));
}

// ---------------- launch ----------------
extern "C" void kernel_launch(void* const* d_in, const int* in_sizes, int n_in,
                              void* d_out, int out_size) {
    const float* x     = (const float*)d_in[0];
    const int*   len   = (const int*)  d_in[1];
    const float* h0    = (const float*)d_in[2];
    const float* c0    = (const float*)d_in[3];
    const float* Wis0  = (const float*)d_in[4];
    const float* bis0  = (const float*)d_in[5];
    const float* Wis1  = (const float*)d_in[6];
    const float* bis1  = (const float*)d_in[7];
    const float* Wih   = (const float*)d_in[8];
    const float* Whh   = (const float*)d_in[9];
    const float* bih   = (const float*)d_in[10];
    const float* bhh   = (const float*)d_in[11];
    const float* Wo    = (const float*)d_in[12];
    const float* bo    = (const float*)d_in[13];
    float* out = (float*)d_out;

    cudaFuncSetAttribute(k_rnn, cudaFuncAttributeMaxDynamicSharedMemorySize, RNN_SMEM);

    k_prep<<<2048, 128>>>(Wis0, bis0, Wis1, bis1, Wih, bih, bhh);
    k_init<<<128, 256>>>(h0, c0);
    k_temb<<<8192, 256>>>(x);
    k_cvtw<<<2048, 256>>>(Wih);
    k_mma<<<dim3(16, 64), 256>>>(x);
    k_rnn<<<RNN_BLOCKS, 256, RNN_SMEM>>>(Whh);
    k_out<<<dim3(64, 14), 128>>>(Wo, bo, len, out);
}

// round 12
// speedup vs baseline: 1.7236x; 1.0560x over previous
#include <cuda_runtime.h>
#include <cuda_bf16.h>
#include <math.h>
#include <stdint.h>

// Problem constants
#define BB   64      // batch
#define TT   128     // seq len
#define HH   512     // hidden
#define NSEQ 128     // B * S (2 segments batched)
#define RNN_BLOCKS 64

// ---------------- scratch (__device__ globals; no allocations) ----------------
__device__ __nv_bfloat16 g_Ah[(size_t)8192 * 1024]; // t_emb hi  [n][1024]
__device__ __nv_bfloat16 g_Al[(size_t)8192 * 1024]; // t_emb lo
__device__ __nv_bfloat16 g_Bh[(size_t)2048 * 1024]; // W_ih[:,512:1536] hi [r][1024]
__device__ __nv_bfloat16 g_Bl[(size_t)2048 * 1024]; // W_ih lo
__device__ float g_gin [(size_t)128 * 128 * 2048];  // [t2][seq][r] fused input gates (+biases)
__device__ __nv_bfloat16 g_hhh[(size_t)128 * 128 * 512]; // [t][seq][k] h history hi
__device__ __nv_bfloat16 g_hhl[(size_t)128 * 128 * 512]; // [t][seq][k] h history lo
__device__ __nv_bfloat16 g_h0h[128 * 512];          // [seq][k] init h hi
__device__ __nv_bfloat16 g_h0l[128 * 512];          // [seq][k] init h lo
__device__ float g_c   [512 * 128];                 // [k][seq] c init
__device__ float g_Mt  [2048 * 16];                 // per-gate-row: {M_e0[8], M_e1[6], cst0, cst1}
__device__ unsigned int g_bar;                      // grid barrier counter

__device__ __forceinline__ float sigf(float x) { return 1.0f / (1.0f + expf(-x)); }

__device__ __forceinline__ uint32_t smem_u32(const void* p) {
    uint32_t a;
    asm("{ .reg .u64 t; cvta.to.shared.u64 t, %1; cvt.u32.u64 %0, t; }" : "=r"(a) : "l"(p));
    return a;
}
__device__ __forceinline__ void ldsm4(uint32_t* r, uint32_t addr) {
    asm volatile("ldmatrix.sync.aligned.m8n8.x4.shared.b16 {%0,%1,%2,%3}, [%4];"
                 : "=r"(r[0]), "=r"(r[1]), "=r"(r[2]), "=r"(r[3]) : "r"(addr));
}
__device__ __forceinline__ void mma16816(float* c, const uint32_t* a, const uint32_t* b) {
    asm volatile("mma.sync.aligned.m16n8k16.row.col.f32.bf16.bf16.f32 "
                 "{%0,%1,%2,%3}, {%4,%5,%6,%7}, {%8,%9}, {%0,%1,%2,%3};"
                 : "+f"(c[0]), "+f"(c[1]), "+f"(c[2]), "+f"(c[3])
                 : "r"(a[0]), "r"(a[1]), "r"(a[2]), "r"(a[3]), "r"(b[0]), "r"(b[1]));
}
#define CP_ASYNC16(dst, src) \
    asm volatile("cp.async.cg.shared.global [%0], [%1], 16;" :: "r"(dst), "l"(src))

// ---------------- K0: fold W_is / biases; write g_Mt[r][16] ----------------
__global__ void k_prep(const float* __restrict__ Wis0, const float* __restrict__ bis0,
                       const float* __restrict__ Wis1, const float* __restrict__ bis1,
                       const float* __restrict__ Wih,  const float* __restrict__ bih,
                       const float* __restrict__ bhh) {
    int r   = blockIdx.x;          // gate row 0..2047
    int tid = threadIdx.x;         // 128
    float acc[16];
#pragma unroll
    for (int j = 0; j < 16; j++) acc[j] = 0.0f;
    const float* wr = Wih + (size_t)r * 1536;      // W_ih row r, cols 0..511
    for (int k = tid; k < 512; k += 128) {
        float w = wr[k];
#pragma unroll
        for (int j = 0; j < 8; j++) acc[j]     += Wis0[k * 8 + j] * w;
#pragma unroll
        for (int j = 0; j < 6; j++) acc[8 + j] += Wis1[k * 6 + j] * w;
        acc[14] += bis0[k] * w;
        acc[15] += bis1[k] * w;
    }
    __shared__ float red[16][128];
#pragma unroll
    for (int j = 0; j < 16; j++) red[j][tid] = acc[j];
    __syncthreads();
    for (int s = 64; s > 0; s >>= 1) {
        if (tid < s) {
#pragma unroll
            for (int j = 0; j < 16; j++) red[j][tid] += red[j][tid + s];
        }
        __syncthreads();
    }
    if (tid < 14) g_Mt[r * 16 + tid] = red[tid][0];
    if (tid == 14) g_Mt[r * 16 + 14] = red[14][0] + bih[r] + bhh[r];
    if (tid == 15) g_Mt[r * 16 + 15] = red[15][0] + bih[r] + bhh[r];
}

// ---------------- K1: init h (bf16 hi/lo, [seq][k]) and c (fp32 [k][seq]); reset barrier ----------------
__global__ void k_init(const float* __restrict__ h0, const float* __restrict__ c0) {
    int idx = blockIdx.x * blockDim.x + threadIdx.x;   // over 64*512
    if (idx == 0) g_bar = 0u;
    if (idx >= 64 * 512) return;
    int b = idx >> 9, k = idx & 511;
    float hv = h0[b * 512 + k], cv = c0[b * 512 + k];
    __nv_bfloat16 hi = __float2bfloat16(hv);
    __nv_bfloat16 lo = __float2bfloat16(hv - __bfloat162float(hi));
    g_h0h[(size_t)b * 512 + k] = hi;  g_h0h[(size_t)(64 + b) * 512 + k] = hi;
    g_h0l[(size_t)b * 512 + k] = lo;  g_h0l[(size_t)(64 + b) * 512 + k] = lo;
    g_c[k * 128 + b] = cv;  g_c[k * 128 + 64 + b] = cv;
}

// ---------------- K2: timestep embeddings, write bf16 hi/lo directly ----------------
__global__ void k_temb(const float* __restrict__ x) {
    int n = blockIdx.x;          // 0..8191 (= b*128 + t)
    int i = threadIdx.x;         // 0..255
    float tc = x[n * 16 + 0];
    float tp = x[n * 16 + 1];
    float f  = expf(-9.210340371976184f * (float)i * (1.0f / 256.0f));
    float s, c;
    __nv_bfloat16* ah = g_Ah + (size_t)n * 1024;
    __nv_bfloat16* al = g_Al + (size_t)n * 1024;
    sincosf(tc * f, &s, &c);
    {
        __nv_bfloat16 h = __float2bfloat16(c);
        ah[i] = h;        al[i] = __float2bfloat16(c - __bfloat162float(h));
        h = __float2bfloat16(s);
        ah[256 + i] = h;  al[256 + i] = __float2bfloat16(s - __bfloat162float(h));
    }
    sincosf(tp * f, &s, &c);
    {
        __nv_bfloat16 h = __float2bfloat16(c);
        ah[512 + i] = h;  al[512 + i] = __float2bfloat16(c - __bfloat162float(h));
        h = __float2bfloat16(s);
        ah[768 + i] = h;  al[768 + i] = __float2bfloat16(s - __bfloat162float(h));
    }
}

// ---------------- K2b: convert W_ih[:,512:1536] to bf16 hi/lo ----------------
__global__ void k_cvtw(const float* __restrict__ Wih) {
    int r = blockIdx.x;          // 0..2047
    for (int k = threadIdx.x; k < 1024; k += 256) {
        float w = Wih[(size_t)r * 1536 + 512 + k];
        __nv_bfloat16 h = __float2bfloat16(w);
        g_Bh[(size_t)r * 1024 + k] = h;
        g_Bl[(size_t)r * 1024 + k] = __float2bfloat16(w - __bfloat162float(h));
    }
}

// ---------------- K3: HMMA bf16 GEMM  gin = t_emb @ W_ih[:,512:1536].T (hi/lo split, 3 products) ----------------
// cp.async 2-stage pipeline. Dynamic smem: stage s @ s*40960, bufs Ah/Al/Bh/Bl @ +0/10240/20480/30720.
#define MPITCH 40
#define MSTAGE 40960
#define MMA_SMEM (2 * MSTAGE)
__global__ __launch_bounds__(256) void k_mma(const float* __restrict__ x) {
    extern __shared__ char dsm[];
    uint32_t sb = smem_u32(dsm);

    int tid = threadIdx.x;
    int warp = tid >> 5, lane = tid & 31;
    int warp_m = warp >> 2;           // 0..1
    int warp_n = warp & 3;            // 0..3
    int bx = blockIdx.x;              // n-tile 0..15
    int by = blockIdx.y;              // m-tile == batch b, 0..63

    const __nv_bfloat16* srcA_h = g_Ah + (size_t)by * 128 * 1024;
    const __nv_bfloat16* srcA_l = g_Al + (size_t)by * 128 * 1024;
    const __nv_bfloat16* srcB_h = g_Bh + (size_t)bx * 128 * 1024;
    const __nv_bfloat16* srcB_l = g_Bl + (size_t)bx * 128 * 1024;

    int la7 = lane & 7, lb = (lane >> 3) & 1, lc = lane >> 4;
    int arow = warp_m * 64 + la7 + lb * 8;
    int acol0 = lc * 8;
    int brow = warp_n * 32 + la7 + lc * 8;
    int bcol0 = lb * 8;

    // load addressing (per thread): 2 reps x 4 buffers, 16B each
    int lrow0 = tid >> 2, lq = tid & 3;
    uint32_t s_off0 = (uint32_t)(lrow0 * 80 + lq * 16);          // bytes within buffer
    uint32_t s_off1 = s_off0 + 64 * 80;                           // rep1: row += 64
    size_t g_off0 = (size_t)lrow0 * 1024 + lq * 8;               // elements
    size_t g_off1 = g_off0 + (size_t)64 * 1024;

#define MISSUE(KC, ST) do {                                                    \
    uint32_t base = sb + (ST) * MSTAGE;                                        \
    size_t gc_ = (size_t)(KC);                                                 \
    CP_ASYNC16(base +         s_off0, srcA_h + g_off0 + gc_);                  \
    CP_ASYNC16(base + 10240 + s_off0, srcA_l + g_off0 + gc_);                  \
    CP_ASYNC16(base + 20480 + s_off0, srcB_h + g_off0 + gc_);                  \
    CP_ASYNC16(base + 30720 + s_off0, srcB_l + g_off0 + gc_);                  \
    CP_ASYNC16(base +         s_off1, srcA_h + g_off1 + gc_);                  \
    CP_ASYNC16(base + 10240 + s_off1, srcA_l + g_off1 + gc_);                  \
    CP_ASYNC16(base + 20480 + s_off1, srcB_h + g_off1 + gc_);                  \
    CP_ASYNC16(base + 30720 + s_off1, srcB_l + g_off1 + gc_);                  \
    asm volatile("cp.async.commit_group;");                                    \
} while (0)

    float acc[4][4][4];
#pragma unroll
    for (int i = 0; i < 4; i++)
#pragma unroll
        for (int j = 0; j < 4; j++)
#pragma unroll
            for (int q = 0; q < 4; q++) acc[i][j][q] = 0.0f;

    MISSUE(0, 0);
    for (int kt = 0; kt < 32; kt++) {
        int st = kt & 1;
        if (kt < 31) {
            MISSUE((kt + 1) * 32, st ^ 1);
            asm volatile("cp.async.wait_group 1;");
        } else {
            asm volatile("cp.async.wait_group 0;");
        }
        __syncthreads();

        uint32_t uAh = sb + st * MSTAGE;
        uint32_t uAl = uAh + 10240;
        uint32_t uBh = uAh + 20480;
        uint32_t uBl = uAh + 30720;

#pragma unroll
        for (int ks = 0; ks < 2; ks++) {
            uint32_t ah[4][4], al[4][4], bh[4][2], bl[4][2];
            int acol = ks * 16 + acol0;
            int bcol = ks * 16 + bcol0;
#pragma unroll
            for (int mi = 0; mi < 4; mi++) {
                uint32_t off = (uint32_t)(((arow + mi * 16) * MPITCH + acol) * 2);
                ldsm4(ah[mi], uAh + off);
                ldsm4(al[mi], uAl + off);
            }
#pragma unroll
            for (int nt = 0; nt < 2; nt++) {
                uint32_t off = (uint32_t)(((brow + nt * 16) * MPITCH + bcol) * 2);
                uint32_t r[4];
                ldsm4(r, uBh + off);
                bh[nt * 2][0] = r[0]; bh[nt * 2][1] = r[1];
                bh[nt * 2 + 1][0] = r[2]; bh[nt * 2 + 1][1] = r[3];
                ldsm4(r, uBl + off);
                bl[nt * 2][0] = r[0]; bl[nt * 2][1] = r[1];
                bl[nt * 2 + 1][0] = r[2]; bl[nt * 2 + 1][1] = r[3];
            }
#pragma unroll
            for (int mi = 0; mi < 4; mi++)
#pragma unroll
                for (int ni = 0; ni < 4; ni++) {
                    mma16816(acc[mi][ni], ah[mi], bh[ni]);
                    mma16816(acc[mi][ni], ah[mi], bl[ni]);
                    mma16816(acc[mi][ni], al[mi], bh[ni]);
                }
        }
        __syncthreads();
    }
#undef MISSUE

    int gr = lane >> 2, gc = (lane & 3) * 2;
#pragma unroll
    for (int mi = 0; mi < 4; mi++) {
#pragma unroll
        for (int half = 0; half < 2; half++) {
            int m = warp_m * 64 + mi * 16 + gr + half * 8;   // original timestep t
            int s2 = m >> 6;
            int t0 = 2 * (m & 63);
            int seq = s2 * 64 + by;
            const float* xr = x + ((size_t)(by * 128 + m)) * 16 + 2;
            float xs[14];
#pragma unroll
            for (int jj = 0; jj < 14; jj++) xs[jj] = xr[jj];
            float* g0 = g_gin + ((size_t)t0 * 128 + seq) * 2048 + bx * 128;
            float* g1 = g0 + (size_t)128 * 2048;
#pragma unroll
            for (int ni = 0; ni < 4; ni++) {
                int lcol = warp_n * 32 + ni * 8 + gc;
                int r = bx * 128 + lcol;
                float b0 = acc[mi][ni][half * 2 + 0];
                float b1 = acc[mi][ni][half * 2 + 1];
                float v0a, v1a, v0b, v1b;
                {
                    const float4* mt = (const float4*)(g_Mt + (size_t)r * 16);
                    float4 m0 = mt[0], m1 = mt[1], m2 = mt[2], m3 = mt[3];
                    v0a = b0 + m3.z + xs[0]*m0.x + xs[1]*m0.y + xs[2]*m0.z + xs[3]*m0.w
                               + xs[4]*m1.x + xs[5]*m1.y + xs[6]*m1.z + xs[7]*m1.w;
                    v1a = b0 + m3.w + xs[8]*m2.x + xs[9]*m2.y + xs[10]*m2.z + xs[11]*m2.w
                               + xs[12]*m3.x + xs[13]*m3.y;
                }
                {
                    const float4* mt = (const float4*)(g_Mt + (size_t)(r + 1) * 16);
                    float4 m0 = mt[0], m1 = mt[1], m2 = mt[2], m3 = mt[3];
                    v0b = b1 + m3.z + xs[0]*m0.x + xs[1]*m0.y + xs[2]*m0.z + xs[3]*m0.w
                               + xs[4]*m1.x + xs[5]*m1.y + xs[6]*m1.z + xs[7]*m1.w;
                    v1b = b1 + m3.w + xs[8]*m2.x + xs[9]*m2.y + xs[10]*m2.z + xs[11]*m2.w
                               + xs[12]*m3.x + xs[13]*m3.y;
                }
                *(float2*)(g0 + lcol) = make_float2(v0a, v0b);
                *(float2*)(g1 + lcol) = make_float2(v1a, v1b);
            }
        }
    }
}

// ---------------- K4: persistent HMMA LSTM recurrence ----------------
// 64 blocks x 256 thr. Block owns 8 hidden units = 32 gate rows (a = g*8+u).
// A = W_hh rows bf16 hi/lo in smem (static). B = h bf16 hi/lo streamed per step
// via double-buffered cp.async. 3-product split: Ah*Bh + Ah*Bl + Al*Bh.
#define AP 520                          // A smem pitch (bf16 elems)
#define BP 136                          // B smem pitch (bf16 elems)
#define GP 136                          // gsm pitch (floats)
#define SA_H 0
#define SA_L 33280
#define SB_H0 66560
#define SB_L0 101376
#define SB_H1 136192
#define SB_L1 171008
#define SGM   205824
#define RNN_SMEM 223232

__global__ __launch_bounds__(256) void k_rnn(const float* __restrict__ Whh) {
    extern __shared__ char sm[];
    uint32_t sb = smem_u32(sm);
    __nv_bfloat16* sAh = (__nv_bfloat16*)(sm + SA_H);
    __nv_bfloat16* sAl = (__nv_bfloat16*)(sm + SA_L);
    float* gsm = (float*)(sm + SGM);

    int tid = threadIdx.x, warp = tid >> 5, lane = tid & 31;
    int warp_m = warp >> 2, warp_n = warp & 3;
    int j8 = blockIdx.x * 8;

    // Stage A: 32 W_hh rows (a = g*8+u -> row g*512 + j8 + u) as bf16 hi/lo, once.
    for (int i = tid; i < 32 * 512; i += 256) {
        int a = i >> 9, k = i & 511;
        float w = Whh[(size_t)((a >> 3) * 512 + j8 + (a & 7)) * 512 + k];
        __nv_bfloat16 hi = __float2bfloat16(w);
        sAh[a * AP + k] = hi;
        sAl[a * AP + k] = __float2bfloat16(w - __bfloat162float(hi));
    }

    // Cell-state ownership: (units j8+u0..+3, seq useq)
    int useq = tid & 127, upair = tid >> 7;
    int u0 = upair * 4;
    float cc[4];
#pragma unroll
    for (int q = 0; q < 4; q++) cc[q] = g_c[(j8 + u0 + q) * 128 + useq];
    __syncthreads();

    int la7 = lane & 7, lb2 = (lane >> 3) & 1, lc2 = lane >> 4;
    int arow = warp_m * 16 + la7 + lb2 * 8;
    int acol0 = lc2 * 8;
    int brow = warp_n * 32 + la7 + lc2 * 8;
    int bcol0 = lb2 * 8;
    uint32_t bufH[2] = {sb + SB_H0, sb + SB_H1};
    uint32_t bufL[2] = {sb + SB_L0, sb + SB_L1};

#define ISSUE_CHUNK(KC, BUF) do {                                              \
    _Pragma("unroll")                                                          \
    for (int j = 0; j < 8; j++) {                                              \
        int gidx = tid * 8 + j;                                                \
        int row = gidx >> 4, seg = gidx & 15;                                  \
        uint32_t so = (uint32_t)(row * (BP * 2) + seg * 16);                   \
        size_t go_ = (size_t)row * 512 + (size_t)(KC) * 128 + seg * 8;         \
        CP_ASYNC16(bufH[BUF] + so, srcH + go_);                                \
        CP_ASYNC16(bufL[BUF] + so, srcL + go_);                                \
    }                                                                          \
    asm volatile("cp.async.commit_group;");                                    \
} while (0)

    for (int t = 0; t < 128; t++) {
        const __nv_bfloat16* srcH = (t == 0) ? g_h0h : (g_hhh + (size_t)(t - 1) * 65536);
        const __nv_bfloat16* srcL = (t == 0) ? g_h0l : (g_hhl + (size_t)(t - 1) * 65536);

        ISSUE_CHUNK(0, 0);

        // Hoisted gin loads: independent of h, overlap their L2 latency with the MMA loop.
        const float* ginb = g_gin + ((size_t)t * 128 + useq) * 2048 + j8 + u0;
        float4 xi = *(const float4*)(ginb);
        float4 xf = *(const float4*)(ginb + 512);
        float4 xg = *(const float4*)(ginb + 1024);
        float4 xo = *(const float4*)(ginb + 1536);

        float acc[4][4];
#pragma unroll
        for (int i = 0; i < 4; i++)
#pragma unroll
            for (int q = 0; q < 4; q++) acc[i][q] = 0.0f;

        for (int kc4 = 0; kc4 < 4; kc4++) {
            int cb = kc4 & 1;
            if (kc4 < 3) {
                ISSUE_CHUNK(kc4 + 1, cb ^ 1);
                asm volatile("cp.async.wait_group 1;");
            } else {
                asm volatile("cp.async.wait_group 0;");
            }
            __syncthreads();
#pragma unroll
            for (int ks = 0; ks < 8; ks++) {
                int acol = kc4 * 128 + ks * 16 + acol0;
                uint32_t aoff = (uint32_t)((arow * AP + acol) * 2);
                uint32_t ah[4], al[4];
                ldsm4(ah, sb + SA_H + aoff);
                ldsm4(al, sb + SA_L + aoff);
                uint32_t bh[4][2], bl[4][2];
#pragma unroll
                for (int nt = 0; nt < 2; nt++) {
                    uint32_t boff = (uint32_t)(((brow + nt * 16) * BP + bcol0 + ks * 16) * 2);
                    uint32_t r[4];
                    ldsm4(r, bufH[cb] + boff);
                    bh[nt * 2][0] = r[0]; bh[nt * 2][1] = r[1];
                    bh[nt * 2 + 1][0] = r[2]; bh[nt * 2 + 1][1] = r[3];
                    ldsm4(r, bufL[cb] + boff);
                    bl[nt * 2][0] = r[0]; bl[nt * 2][1] = r[1];
                    bl[nt * 2 + 1][0] = r[2]; bl[nt * 2 + 1][1] = r[3];
                }
#pragma unroll
                for (int ni = 0; ni < 4; ni++) {
                    mma16816(acc[ni], ah, bh[ni]);
                    mma16816(acc[ni], ah, bl[ni]);
                    mma16816(acc[ni], al, bh[ni]);
                }
            }
            __syncthreads();
        }

        // Store gate sums to gsm[a][seq]
        int r0 = warp_m * 16 + (lane >> 2);
        int c0 = warp_n * 32 + (lane & 3) * 2;
#pragma unroll
        for (int ni = 0; ni < 4; ni++) {
            *(float2*)&gsm[r0 * GP + c0 + ni * 8]       = make_float2(acc[ni][0], acc[ni][1]);
            *(float2*)&gsm[(r0 + 8) * GP + c0 + ni * 8] = make_float2(acc[ni][2], acc[ni][3]);
        }
        __syncthreads();

        // Update phase
        float xiv[4] = {xi.x, xi.y, xi.z, xi.w};
        float xfv[4] = {xf.x, xf.y, xf.z, xf.w};
        float xgv[4] = {xg.x, xg.y, xg.z, xg.w};
        float xov[4] = {xo.x, xo.y, xo.z, xo.w};
        float hn[4];
#pragma unroll
        for (int q = 0; q < 4; q++) {
            int u = u0 + q;
            float gi = gsm[u * GP + useq]        + xiv[q];
            float gf = gsm[(8 + u) * GP + useq]  + xfv[q];
            float gg = gsm[(16 + u) * GP + useq] + xgv[q];
            float go = gsm[(24 + u) * GP + useq] + xov[q];
            cc[q] = sigf(gf) * cc[q] + sigf(gi) * tanhf(gg);
            hn[q] = sigf(go) * tanhf(cc[q]);
        }
        __align__(8) __nv_bfloat16 hhv[4], hlv[4];
#pragma unroll
        for (int q = 0; q < 4; q++) {
            __nv_bfloat16 hi = __float2bfloat16(hn[q]);
            hhv[q] = hi;
            hlv[q] = __float2bfloat16(hn[q] - __bfloat162float(hi));
        }
        size_t hb = ((size_t)t * 128 + useq) * 512 + j8 + u0;
        *(uint2*)(g_hhh + hb) = *(uint2*)hhv;
        *(uint2*)(g_hhl + hb) = *(uint2*)hlv;

        if (t < 127) {
            __syncthreads();
            if (tid == 0) {
                __threadfence();
                atomicAdd(&g_bar, 1u);
                unsigned target = (unsigned)(t + 1) * RNN_BLOCKS;
                volatile unsigned int* vb = &g_bar;
                while (*vb < target) { }
            }
            __syncthreads();
        }
    }
#undef ISSUE_CHUNK
}

// ---------------- K5: gather h at lengths-1 (hi+lo), output linear + sigmoid ----------------
__global__ void k_out(const float* __restrict__ Wo, const float* __restrict__ bo,
                      const int* __restrict__ lengths, float* __restrict__ out) {
    int b = blockIdx.x, o = blockIdx.y;
    int tid = threadIdx.x;             // 128
    int t = lengths[b] - 1;
    const __nv_bfloat16* ph = g_hhh + (size_t)t * 65536;
    const __nv_bfloat16* pl = g_hhl + (size_t)t * 65536;
    float acc = 0.0f;
    for (int k = tid; k < 512; k += 128) {
        float h0v = __bfloat162float(ph[(size_t)b * 512 + k])
                  + __bfloat162float(pl[(size_t)b * 512 + k]);
        float h1v = __bfloat162float(ph[(size_t)(64 + b) * 512 + k])
                  + __bfloat162float(pl[(size_t)(64 + b) * 512 + k]);
        acc += Wo[o * 1024 + k] * h0v + Wo[o * 1024 + 512 + k] * h1v;
    }
    __shared__ float red[128];
    red[tid] = acc;
    __syncthreads();
    for (int s = 64; s > 0; s >>= 1) {
        if (tid < s) red[tid] += red[tid + s];
        __syncthreads();
    }
    if (tid == 0) out[b * 14 + o] = 1.0f / (1.0f + expf(-(red[0] + bo[o])));
}

// ---------------- launch ----------------
extern "C" void kernel_launch(void* const* d_in, const int* in_sizes, int n_in,
                              void* d_out, int out_size) {
    const float* x     = (const float*)d_in[0];
    const int*   len   = (const int*)  d_in[1];
    const float* h0    = (const float*)d_in[2];
    const float* c0    = (const float*)d_in[3];
    const float* Wis0  = (const float*)d_in[4];
    const float* bis0  = (const float*)d_in[5];
    const float* Wis1  = (const float*)d_in[6];
    const float* bis1  = (const float*)d_in[7];
    const float* Wih   = (const float*)d_in[8];
    const float* Whh   = (const float*)d_in[9];
    const float* bih   = (const float*)d_in[10];
    const float* bhh   = (const float*)d_in[11];
    const float* Wo    = (const float*)d_in[12];
    const float* bo    = (const float*)d_in[13];
    float* out = (float*)d_out;

    cudaFuncSetAttribute(k_rnn, cudaFuncAttributeMaxDynamicSharedMemorySize, RNN_SMEM);
    cudaFuncSetAttribute(k_mma, cudaFuncAttributeMaxDynamicSharedMemorySize, MMA_SMEM);

    k_prep<<<2048, 128>>>(Wis0, bis0, Wis1, bis1, Wih, bih, bhh);
    k_init<<<128, 256>>>(h0, c0);
    k_temb<<<8192, 256>>>(x);
    k_cvtw<<<2048, 256>>>(Wih);
    k_mma<<<dim3(16, 64), 256, MMA_SMEM>>>(x);
    k_rnn<<<RNN_BLOCKS, 256, RNN_SMEM>>>(Whh);
    k_out<<<dim3(64, 14), 128>>>(Wo, bo, len, out);
}

// round 13
// speedup vs baseline: 1.8769x; 1.0889x over previous
#include <cuda_runtime.h>
#include <cuda_bf16.h>
#include <math.h>
#include <stdint.h>

// Problem constants
#define BB   64      // batch
#define TT   128     // seq len
#define HH   512     // hidden
#define NSEQ 128     // B * S (2 segments batched)
#define RNN_BLOCKS 128

// ---------------- scratch (__device__ globals; no allocations) ----------------
__device__ __nv_bfloat16 g_Ah[(size_t)8192 * 1024]; // t_emb hi  [n][1024]
__device__ __nv_bfloat16 g_Al[(size_t)8192 * 1024]; // t_emb lo
__device__ __nv_bfloat16 g_Bh[(size_t)2048 * 1024]; // W_ih[:,512:1536] hi [r][1024]
__device__ __nv_bfloat16 g_Bl[(size_t)2048 * 1024]; // W_ih lo
__device__ float g_gin [(size_t)128 * 128 * 2048];  // [t2][seq][r] fused input gates (+biases)
__device__ __nv_bfloat16 g_hhh[(size_t)128 * 128 * 512]; // [t][seq][k] h history hi
__device__ __nv_bfloat16 g_hhl[(size_t)128 * 128 * 512]; // [t][seq][k] h history lo
__device__ __nv_bfloat16 g_h0h[128 * 512];          // [seq][k] init h hi
__device__ __nv_bfloat16 g_h0l[128 * 512];          // [seq][k] init h lo
__device__ float g_c   [512 * 128];                 // [k][seq] c init
__device__ float g_Mt  [2048 * 16];                 // per-gate-row: {M_e0[8], M_e1[6], cst0, cst1}
__device__ unsigned int g_bar;                      // grid barrier counter

__device__ __forceinline__ float sigf(float x) { return 1.0f / (1.0f + expf(-x)); }

__device__ __forceinline__ uint32_t smem_u32(const void* p) {
    uint32_t a;
    asm("{ .reg .u64 t; cvta.to.shared.u64 t, %1; cvt.u32.u64 %0, t; }" : "=r"(a) : "l"(p));
    return a;
}
__device__ __forceinline__ void ldsm4(uint32_t* r, uint32_t addr) {
    asm volatile("ldmatrix.sync.aligned.m8n8.x4.shared.b16 {%0,%1,%2,%3}, [%4];"
                 : "=r"(r[0]), "=r"(r[1]), "=r"(r[2]), "=r"(r[3]) : "r"(addr));
}
__device__ __forceinline__ void mma16816(float* c, const uint32_t* a, const uint32_t* b) {
    asm volatile("mma.sync.aligned.m16n8k16.row.col.f32.bf16.bf16.f32 "
                 "{%0,%1,%2,%3}, {%4,%5,%6,%7}, {%8,%9}, {%0,%1,%2,%3};"
                 : "+f"(c[0]), "+f"(c[1]), "+f"(c[2]), "+f"(c[3])
                 : "r"(a[0]), "r"(a[1]), "r"(a[2]), "r"(a[3]), "r"(b[0]), "r"(b[1]));
}
#define CP_ASYNC16(dst, src) \
    asm volatile("cp.async.cg.shared.global [%0], [%1], 16;" :: "r"(dst), "l"(src))

// ---------------- K0: fold W_is / biases; write g_Mt[r][16] ----------------
__global__ void k_prep(const float* __restrict__ Wis0, const float* __restrict__ bis0,
                       const float* __restrict__ Wis1, const float* __restrict__ bis1,
                       const float* __restrict__ Wih,  const float* __restrict__ bih,
                       const float* __restrict__ bhh) {
    int r   = blockIdx.x;          // gate row 0..2047
    int tid = threadIdx.x;         // 128
    float acc[16];
#pragma unroll
    for (int j = 0; j < 16; j++) acc[j] = 0.0f;
    const float* wr = Wih + (size_t)r * 1536;      // W_ih row r, cols 0..511
    for (int k = tid; k < 512; k += 128) {
        float w = wr[k];
#pragma unroll
        for (int j = 0; j < 8; j++) acc[j]     += Wis0[k * 8 + j] * w;
#pragma unroll
        for (int j = 0; j < 6; j++) acc[8 + j] += Wis1[k * 6 + j] * w;
        acc[14] += bis0[k] * w;
        acc[15] += bis1[k] * w;
    }
    __shared__ float red[16][128];
#pragma unroll
    for (int j = 0; j < 16; j++) red[j][tid] = acc[j];
    __syncthreads();
    for (int s = 64; s > 0; s >>= 1) {
        if (tid < s) {
#pragma unroll
            for (int j = 0; j < 16; j++) red[j][tid] += red[j][tid + s];
        }
        __syncthreads();
    }
    if (tid < 14) g_Mt[r * 16 + tid] = red[tid][0];
    if (tid == 14) g_Mt[r * 16 + 14] = red[14][0] + bih[r] + bhh[r];
    if (tid == 15) g_Mt[r * 16 + 15] = red[15][0] + bih[r] + bhh[r];
}

// ---------------- K1 merged: temb (blocks 0..8191) | cvtw (8192..10239) | init (10240..10367) ----------------
__global__ void k_pre(const float* __restrict__ x, const float* __restrict__ Wih,
                      const float* __restrict__ h0, const float* __restrict__ c0) {
    int bid = blockIdx.x;
    int tid = threadIdx.x;   // 256
    if (bid < 8192) {
        // timestep embeddings, bf16 hi/lo
        int n = bid;
        float tc = x[n * 16 + 0];
        float tp = x[n * 16 + 1];
        float f  = expf(-9.210340371976184f * (float)tid * (1.0f / 256.0f));
        float s, c;
        __nv_bfloat16* ah = g_Ah + (size_t)n * 1024;
        __nv_bfloat16* al = g_Al + (size_t)n * 1024;
        sincosf(tc * f, &s, &c);
        {
            __nv_bfloat16 h = __float2bfloat16(c);
            ah[tid] = h;        al[tid] = __float2bfloat16(c - __bfloat162float(h));
            h = __float2bfloat16(s);
            ah[256 + tid] = h;  al[256 + tid] = __float2bfloat16(s - __bfloat162float(h));
        }
        sincosf(tp * f, &s, &c);
        {
            __nv_bfloat16 h = __float2bfloat16(c);
            ah[512 + tid] = h;  al[512 + tid] = __float2bfloat16(c - __bfloat162float(h));
            h = __float2bfloat16(s);
            ah[768 + tid] = h;  al[768 + tid] = __float2bfloat16(s - __bfloat162float(h));
        }
    } else if (bid < 10240) {
        // convert W_ih[:,512:1536] to bf16 hi/lo
        int r = bid - 8192;
        for (int k = tid; k < 1024; k += 256) {
            float w = Wih[(size_t)r * 1536 + 512 + k];
            __nv_bfloat16 h = __float2bfloat16(w);
            g_Bh[(size_t)r * 1024 + k] = h;
            g_Bl[(size_t)r * 1024 + k] = __float2bfloat16(w - __bfloat162float(h));
        }
    } else {
        // init h (bf16 hi/lo, [seq][k]) and c (fp32 [k][seq]); reset barrier
        int idx = (bid - 10240) * 256 + tid;     // over 64*512
        if (idx == 0) g_bar = 0u;
        int b = idx >> 9, k = idx & 511;
        float hv = h0[b * 512 + k], cv = c0[b * 512 + k];
        __nv_bfloat16 hi = __float2bfloat16(hv);
        __nv_bfloat16 lo = __float2bfloat16(hv - __bfloat162float(hi));
        g_h0h[(size_t)b * 512 + k] = hi;  g_h0h[(size_t)(64 + b) * 512 + k] = hi;
        g_h0l[(size_t)b * 512 + k] = lo;  g_h0l[(size_t)(64 + b) * 512 + k] = lo;
        g_c[k * 128 + b] = cv;  g_c[k * 128 + 64 + b] = cv;
    }
}

// ---------------- K3: HMMA bf16 GEMM  gin = t_emb @ W_ih[:,512:1536].T (hi/lo split, 3 products) ----------------
// Grid (32, 64): M=128 (batch by), N=64 (bx). 8 warps (2m x 4n), warp tile 64x16.
// 3-stage cp.async pipeline; 2 blocks/SM.
#define MPITCH 40
#define MSTAGE 30720
#define MMA_SMEM (3 * MSTAGE)
__global__ __launch_bounds__(256, 2) void k_mma(const float* __restrict__ x) {
    extern __shared__ char dsm[];
    uint32_t sb = smem_u32(dsm);

    int tid = threadIdx.x;
    int warp = tid >> 5, lane = tid & 31;
    int warp_m = warp >> 2;           // 0..1
    int warp_n = warp & 3;            // 0..3
    int bx = blockIdx.x;              // n-tile 0..31 (64 gate rows each)
    int by = blockIdx.y;              // m-tile == batch b, 0..63

    const __nv_bfloat16* srcA_h = g_Ah + (size_t)by * 128 * 1024;
    const __nv_bfloat16* srcA_l = g_Al + (size_t)by * 128 * 1024;
    const __nv_bfloat16* srcB_h = g_Bh + (size_t)bx * 64 * 1024;
    const __nv_bfloat16* srcB_l = g_Bl + (size_t)bx * 64 * 1024;

    int la7 = lane & 7, lb = (lane >> 3) & 1, lc = lane >> 4;
    int arow = warp_m * 64 + la7 + lb * 8;
    int acol0 = lc * 8;
    int brow = warp_n * 16 + la7 + lc * 8;
    int bcol0 = lb * 8;

    // load addressing
    uint32_t a_off0 = (uint32_t)((tid >> 2) * 80 + (tid & 3) * 16);
    uint32_t a_off1 = a_off0 + 64 * 80;
    size_t a_g0 = (size_t)(tid >> 2) * 1024 + (tid & 3) * 8;
    size_t a_g1 = a_g0 + (size_t)64 * 1024;
    uint32_t b_off = a_off0;                      // rows 0..63
    size_t b_g = a_g0;

#define MISSUE(KC, ST) do {                                                    \
    uint32_t base = sb + (ST) * MSTAGE;                                        \
    size_t gc_ = (size_t)(KC);                                                 \
    CP_ASYNC16(base +         a_off0, srcA_h + a_g0 + gc_);                    \
    CP_ASYNC16(base + 10240 + a_off0, srcA_l + a_g0 + gc_);                    \
    CP_ASYNC16(base +         a_off1, srcA_h + a_g1 + gc_);                    \
    CP_ASYNC16(base + 10240 + a_off1, srcA_l + a_g1 + gc_);                    \
    CP_ASYNC16(base + 20480 + b_off, srcB_h + b_g + gc_);                      \
    CP_ASYNC16(base + 25600 + b_off, srcB_l + b_g + gc_);                      \
    asm volatile("cp.async.commit_group;");                                    \
} while (0)

    float acc[4][2][4];
#pragma unroll
    for (int i = 0; i < 4; i++)
#pragma unroll
        for (int j = 0; j < 2; j++)
#pragma unroll
            for (int q = 0; q < 4; q++) acc[i][j][q] = 0.0f;

    MISSUE(0, 0);
    MISSUE(32, 1);
    for (int kt = 0; kt < 32; kt++) {
        int st = kt % 3;
        if (kt < 30) {
            MISSUE((kt + 2) * 32, (kt + 2) % 3);
            asm volatile("cp.async.wait_group 2;");
        } else if (kt == 30) {
            asm volatile("cp.async.wait_group 1;");
        } else {
            asm volatile("cp.async.wait_group 0;");
        }
        __syncthreads();

        uint32_t uAh = sb + st * MSTAGE;
        uint32_t uAl = uAh + 10240;
        uint32_t uBh = uAh + 20480;
        uint32_t uBl = uAh + 25600;

#pragma unroll
        for (int ks = 0; ks < 2; ks++) {
            uint32_t ah[4][4], al[4][4], bh[2][2], bl[2][2];
            int acol = ks * 16 + acol0;
            int bcol = ks * 16 + bcol0;
#pragma unroll
            for (int mi = 0; mi < 4; mi++) {
                uint32_t off = (uint32_t)(((arow + mi * 16) * MPITCH + acol) * 2);
                ldsm4(ah[mi], uAh + off);
                ldsm4(al[mi], uAl + off);
            }
            {
                uint32_t off = (uint32_t)((brow * MPITCH + bcol) * 2);
                uint32_t r[4];
                ldsm4(r, uBh + off);
                bh[0][0] = r[0]; bh[0][1] = r[1]; bh[1][0] = r[2]; bh[1][1] = r[3];
                ldsm4(r, uBl + off);
                bl[0][0] = r[0]; bl[0][1] = r[1]; bl[1][0] = r[2]; bl[1][1] = r[3];
            }
#pragma unroll
            for (int mi = 0; mi < 4; mi++)
#pragma unroll
                for (int ni = 0; ni < 2; ni++) {
                    mma16816(acc[mi][ni], ah[mi], bh[ni]);
                    mma16816(acc[mi][ni], ah[mi], bl[ni]);
                    mma16816(acc[mi][ni], al[mi], bh[ni]);
                }
        }
        __syncthreads();
    }
#undef MISSUE

    int gr = lane >> 2, gc = (lane & 3) * 2;
#pragma unroll
    for (int mi = 0; mi < 4; mi++) {
#pragma unroll
        for (int half = 0; half < 2; half++) {
            int m = warp_m * 64 + mi * 16 + gr + half * 8;   // original timestep t
            int s2 = m >> 6;
            int t0 = 2 * (m & 63);
            int seq = s2 * 64 + by;
            const float* xr = x + ((size_t)(by * 128 + m)) * 16 + 2;
            float xs[14];
#pragma unroll
            for (int jj = 0; jj < 14; jj++) xs[jj] = xr[jj];
            float* g0 = g_gin + ((size_t)t0 * 128 + seq) * 2048 + bx * 64;
            float* g1 = g0 + (size_t)128 * 2048;
#pragma unroll
            for (int ni = 0; ni < 2; ni++) {
                int lcol = warp_n * 16 + ni * 8 + gc;
                int r = bx * 64 + lcol;
                float b0 = acc[mi][ni][half * 2 + 0];
                float b1 = acc[mi][ni][half * 2 + 1];
                float v0a, v1a, v0b, v1b;
                {
                    const float4* mt = (const float4*)(g_Mt + (size_t)r * 16);
                    float4 m0 = mt[0], m1 = mt[1], m2 = mt[2], m3 = mt[3];
                    v0a = b0 + m3.z + xs[0]*m0.x + xs[1]*m0.y + xs[2]*m0.z + xs[3]*m0.w
                               + xs[4]*m1.x + xs[5]*m1.y + xs[6]*m1.z + xs[7]*m1.w;
                    v1a = b0 + m3.w + xs[8]*m2.x + xs[9]*m2.y + xs[10]*m2.z + xs[11]*m2.w
                               + xs[12]*m3.x + xs[13]*m3.y;
                }
                {
                    const float4* mt = (const float4*)(g_Mt + (size_t)(r + 1) * 16);
                    float4 m0 = mt[0], m1 = mt[1], m2 = mt[2], m3 = mt[3];
                    v0b = b1 + m3.z + xs[0]*m0.x + xs[1]*m0.y + xs[2]*m0.z + xs[3]*m0.w
                               + xs[4]*m1.x + xs[5]*m1.y + xs[6]*m1.z + xs[7]*m1.w;
                    v1b = b1 + m3.w + xs[8]*m2.x + xs[9]*m2.y + xs[10]*m2.z + xs[11]*m2.w
                               + xs[12]*m3.x + xs[13]*m3.y;
                }
                *(float2*)(g0 + lcol) = make_float2(v0a, v0b);
                *(float2*)(g1 + lcol) = make_float2(v1a, v1b);
            }
        }
    }
}

// ---------------- K4: persistent HMMA LSTM recurrence ----------------
// 128 blocks x 256 thr. Block owns 4 hidden units = 16 gate rows (a = g*4+u).
// A = W_hh rows bf16 hi/lo in smem (static). B = h bf16 hi/lo streamed per step
// via double-buffered cp.async. Warp w computes all 16 gate rows x seqs [w*16, w*16+16).
#define AP 520                          // A smem pitch (bf16 elems)
#define BP 136                          // B smem pitch (bf16 elems)
#define GP 136                          // gsm pitch (floats)
#define SA_H 0
#define SA_L 16640
#define SB_H0 33280
#define SB_L0 68096
#define SB_H1 102912
#define SB_L1 137728
#define SGM   172544
#define RNN_SMEM 181248

__global__ __launch_bounds__(256) void k_rnn(const float* __restrict__ Whh) {
    extern __shared__ char sm[];
    uint32_t sb = smem_u32(sm);
    __nv_bfloat16* sAh = (__nv_bfloat16*)(sm + SA_H);
    __nv_bfloat16* sAl = (__nv_bfloat16*)(sm + SA_L);
    float* gsm = (float*)(sm + SGM);

    int tid = threadIdx.x, warp = tid >> 5, lane = tid & 31;
    int j4 = blockIdx.x * 4;

    // Stage A: 16 W_hh rows (a = g*4+u -> row g*512 + j4 + u) as bf16 hi/lo, once.
    for (int i = tid; i < 16 * 512; i += 256) {
        int a = i >> 9, k = i & 511;
        float w = Whh[(size_t)((a >> 2) * 512 + j4 + (a & 3)) * 512 + k];
        __nv_bfloat16 hi = __float2bfloat16(w);
        sAh[a * AP + k] = hi;
        sAl[a * AP + k] = __float2bfloat16(w - __bfloat162float(hi));
    }

    // Cell-state ownership: (units j4+u0, j4+u0+1; seq useq)
    int useq = tid & 127, u0 = (tid >> 7) * 2;
    float cc[2];
    cc[0] = g_c[(j4 + u0) * 128 + useq];
    cc[1] = g_c[(j4 + u0 + 1) * 128 + useq];
    __syncthreads();

    int la7 = lane & 7, lb2 = (lane >> 3) & 1, lc2 = lane >> 4;
    int arow = la7 + lb2 * 8;
    int acol0 = lc2 * 8;
    int brow = warp * 16 + la7 + lc2 * 8;
    int bcol0 = lb2 * 8;
    uint32_t bufH[2] = {sb + SB_H0, sb + SB_H1};
    uint32_t bufL[2] = {sb + SB_L0, sb + SB_L1};

#define ISSUE_CHUNK(KC, BUF) do {                                              \
    _Pragma("unroll")                                                          \
    for (int j = 0; j < 8; j++) {                                              \
        int gidx = tid * 8 + j;                                                \
        int row = gidx >> 4, seg = gidx & 15;                                  \
        uint32_t so = (uint32_t)(row * (BP * 2) + seg * 16);                   \
        size_t go_ = (size_t)row * 512 + (size_t)(KC) * 128 + seg * 8;         \
        CP_ASYNC16(bufH[BUF] + so, srcH + go_);                                \
        CP_ASYNC16(bufL[BUF] + so, srcL + go_);                                \
    }                                                                          \
    asm volatile("cp.async.commit_group;");                                    \
} while (0)

    for (int t = 0; t < 128; t++) {
        const __nv_bfloat16* srcH = (t == 0) ? g_h0h : (g_hhh + (size_t)(t - 1) * 65536);
        const __nv_bfloat16* srcL = (t == 0) ? g_h0l : (g_hhl + (size_t)(t - 1) * 65536);

        ISSUE_CHUNK(0, 0);

        // Hoisted gin loads: independent of h, overlap their latency with the MMA loop.
        const float* ginb = g_gin + ((size_t)t * 128 + useq) * 2048 + j4 + u0;
        float2 xi = *(const float2*)(ginb);
        float2 xf = *(const float2*)(ginb + 512);
        float2 xg = *(const float2*)(ginb + 1024);
        float2 xo = *(const float2*)(ginb + 1536);

        float acc0[4] = {0, 0, 0, 0}, acc1[4] = {0, 0, 0, 0};

        for (int kc4 = 0; kc4 < 4; kc4++) {
            int cb = kc4 & 1;
            if (kc4 < 3) {
                ISSUE_CHUNK(kc4 + 1, cb ^ 1);
                asm volatile("cp.async.wait_group 1;");
            } else {
                asm volatile("cp.async.wait_group 0;");
            }
            __syncthreads();
#pragma unroll
            for (int ks = 0; ks < 8; ks++) {
                int acol = kc4 * 128 + ks * 16 + acol0;
                uint32_t aoff = (uint32_t)((arow * AP + acol) * 2);
                uint32_t ah[4], al[4];
                ldsm4(ah, sb + SA_H + aoff);
                ldsm4(al, sb + SA_L + aoff);
                uint32_t boff = (uint32_t)((brow * BP + bcol0 + ks * 16) * 2);
                uint32_t r[4], bh0[2], bh1[2], bl0[2], bl1[2];
                ldsm4(r, bufH[cb] + boff);
                bh0[0] = r[0]; bh0[1] = r[1]; bh1[0] = r[2]; bh1[1] = r[3];
                ldsm4(r, bufL[cb] + boff);
                bl0[0] = r[0]; bl0[1] = r[1]; bl1[0] = r[2]; bl1[1] = r[3];
                mma16816(acc0, ah, bh0);
                mma16816(acc0, ah, bl0);
                mma16816(acc0, al, bh0);
                mma16816(acc1, ah, bh1);
                mma16816(acc1, ah, bl1);
                mma16816(acc1, al, bh1);
            }
            __syncthreads();
        }

        // Store gate sums to gsm[a][seq]
        int gr = lane >> 2, gc = (lane & 3) * 2;
        *(float2*)&gsm[gr * GP + warp * 16 + gc]           = make_float2(acc0[0], acc0[1]);
        *(float2*)&gsm[(gr + 8) * GP + warp * 16 + gc]     = make_float2(acc0[2], acc0[3]);
        *(float2*)&gsm[gr * GP + warp * 16 + 8 + gc]       = make_float2(acc1[0], acc1[1]);
        *(float2*)&gsm[(gr + 8) * GP + warp * 16 + 8 + gc] = make_float2(acc1[2], acc1[3]);
        __syncthreads();

        // Update phase: thread handles (seq=useq, units u0, u0+1)
        float xiv[2] = {xi.x, xi.y};
        float xfv[2] = {xf.x, xf.y};
        float xgv[2] = {xg.x, xg.y};
        float xov[2] = {xo.x, xo.y};
        float hn[2];
#pragma unroll
        for (int q = 0; q < 2; q++) {
            int u = u0 + q;
            float gi = gsm[u * GP + useq]        + xiv[q];
            float gf = gsm[(4 + u) * GP + useq]  + xfv[q];
            float gg = gsm[(8 + u) * GP + useq]  + xgv[q];
            float go = gsm[(12 + u) * GP + useq] + xov[q];
            cc[q] = sigf(gf) * cc[q] + sigf(gi) * tanhf(gg);
            hn[q] = sigf(go) * tanhf(cc[q]);
        }
        __align__(4) __nv_bfloat16 hhv[2], hlv[2];
#pragma unroll
        for (int q = 0; q < 2; q++) {
            __nv_bfloat16 hi = __float2bfloat16(hn[q]);
            hhv[q] = hi;
            hlv[q] = __float2bfloat16(hn[q] - __bfloat162float(hi));
        }
        size_t hb = ((size_t)t * 128 + useq) * 512 + j4 + u0;
        *(uint32_t*)(g_hhh + hb) = *(uint32_t*)hhv;
        *(uint32_t*)(g_hhl + hb) = *(uint32_t*)hlv;

        if (t < 127) {
            __syncthreads();
            if (tid == 0) {
                __threadfence();
                atomicAdd(&g_bar, 1u);
                unsigned target = (unsigned)(t + 1) * RNN_BLOCKS;
                volatile unsigned int* vb = &g_bar;
                while (*vb < target) { }
            }
            __syncthreads();
        }
    }
#undef ISSUE_CHUNK
}

// ---------------- K5: gather h at lengths-1 (hi+lo), output linear + sigmoid ----------------
__global__ void k_out(const float* __restrict__ Wo, const float* __restrict__ bo,
                      const int* __restrict__ lengths, float* __restrict__ out) {
    int b = blockIdx.x, o = blockIdx.y;
    int tid = threadIdx.x;             // 128
    int t = lengths[b] - 1;
    const __nv_bfloat16* ph = g_hhh + (size_t)t * 65536;
    const __nv_bfloat16* pl = g_hhl + (size_t)t * 65536;
    float acc = 0.0f;
    for (int k = tid; k < 512; k += 128) {
        float h0v = __bfloat162float(ph[(size_t)b * 512 + k])
                  + __bfloat162float(pl[(size_t)b * 512 + k]);
        float h1v = __bfloat162float(ph[(size_t)(64 + b) * 512 + k])
                  + __bfloat162float(pl[(size_t)(64 + b) * 512 + k]);
        acc += Wo[o * 1024 + k] * h0v + Wo[o * 1024 + 512 + k] * h1v;
    }
    __shared__ float red[128];
    red[tid] = acc;
    __syncthreads();
    for (int s = 64; s > 0; s >>= 1) {
        if (tid < s) red[tid] += red[tid + s];
        __syncthreads();
    }
    if (tid == 0) out[b * 14 + o] = 1.0f / (1.0f + expf(-(red[0] + bo[o])));
}

// ---------------- launch ----------------
extern "C" void kernel_launch(void* const* d_in, const int* in_sizes, int n_in,
                              void* d_out, int out_size) {
    const float* x     = (const float*)d_in[0];
    const int*   len   = (const int*)  d_in[1];
    const float* h0    = (const float*)d_in[2];
    const float* c0    = (const float*)d_in[3];
    const float* Wis0  = (const float*)d_in[4];
    const float* bis0  = (const float*)d_in[5];
    const float* Wis1  = (const float*)d_in[6];
    const float* bis1  = (const float*)d_in[7];
    const float* Wih   = (const float*)d_in[8];
    const float* Whh   = (const float*)d_in[9];
    const float* bih   = (const float*)d_in[10];
    const float* bhh   = (const float*)d_in[11];
    const float* Wo    = (const float*)d_in[12];
    const float* bo    = (const float*)d_in[13];
    float* out = (float*)d_out;

    cudaFuncSetAttribute(k_rnn, cudaFuncAttributeMaxDynamicSharedMemorySize, RNN_SMEM);
    cudaFuncSetAttribute(k_mma, cudaFuncAttributeMaxDynamicSharedMemorySize, MMA_SMEM);

    k_prep<<<2048, 128>>>(Wis0, bis0, Wis1, bis1, Wih, bih, bhh);
    k_pre<<<10368, 256>>>(x, Wih, h0, c0);
    k_mma<<<dim3(32, 64), 256, MMA_SMEM>>>(x);
    k_rnn<<<RNN_BLOCKS, 256, RNN_SMEM>>>(Whh);
    k_out<<<dim3(64, 14), 128>>>(Wo, bo, len, out);
}

// round 14
// speedup vs baseline: 3.4925x; 1.8608x over previous
#include <cuda_runtime.h>
#include <cuda_bf16.h>
#include <math.h>
#include <stdint.h>

// Problem constants
#define BB   64      // batch
#define TT   128     // seq len
#define HH   512     // hidden
#define NSEQ 128     // B * S (2 segments batched)
#define RNN_BLOCKS 128

// ---------------- scratch (__device__ globals; no allocations) ----------------
__device__ __nv_bfloat16 g_Ah[(size_t)8192 * 1024]; // t_emb hi  [n][1024]
__device__ __nv_bfloat16 g_Al[(size_t)8192 * 1024]; // t_emb lo
__device__ __nv_bfloat16 g_Bh[(size_t)2048 * 1024]; // W_ih[:,512:1536] hi [r][1024]
__device__ __nv_bfloat16 g_Bl[(size_t)2048 * 1024]; // W_ih lo
__device__ float g_gin [(size_t)128 * 128 * 2048];  // [t2][seq][r] fused input gates (+biases)
__device__ __nv_bfloat16 g_hhh[(size_t)128 * 128 * 512]; // [t][seq][k] h history hi
__device__ __nv_bfloat16 g_hhl[(size_t)128 * 128 * 512]; // [t][seq][k] h history lo
__device__ __nv_bfloat16 g_h0h[128 * 512];          // [seq][k] init h hi
__device__ __nv_bfloat16 g_h0l[128 * 512];          // [seq][k] init h lo
__device__ float g_c   [512 * 128];                 // [k][seq] c init
__device__ float g_Mt  [2048 * 16];                 // per-gate-row: {M_e0[8], M_e1[6], cst0, cst1}
__device__ unsigned int g_bar;                      // grid barrier counter

__device__ __forceinline__ float sigf(float x) { return 1.0f / (1.0f + expf(-x)); }

__device__ __forceinline__ uint32_t smem_u32(const void* p) {
    uint32_t a;
    asm("{ .reg .u64 t; cvta.to.shared.u64 t, %1; cvt.u32.u64 %0, t; }" : "=r"(a) : "l"(p));
    return a;
}
__device__ __forceinline__ void ldsm4(uint32_t* r, uint32_t addr) {
    asm volatile("ldmatrix.sync.aligned.m8n8.x4.shared.b16 {%0,%1,%2,%3}, [%4];"
                 : "=r"(r[0]), "=r"(r[1]), "=r"(r[2]), "=r"(r[3]) : "r"(addr));
}
__device__ __forceinline__ void mma16816(float* c, const uint32_t* a, const uint32_t* b) {
    asm volatile("mma.sync.aligned.m16n8k16.row.col.f32.bf16.bf16.f32 "
                 "{%0,%1,%2,%3}, {%4,%5,%6,%7}, {%8,%9}, {%0,%1,%2,%3};"
                 : "+f"(c[0]), "+f"(c[1]), "+f"(c[2]), "+f"(c[3])
                 : "r"(a[0]), "r"(a[1]), "r"(a[2]), "r"(a[3]), "r"(b[0]), "r"(b[1]));
}
#define CP_ASYNC16(dst, src) \
    asm volatile("cp.async.cg.shared.global [%0], [%1], 16;" :: "r"(dst), "l"(src))

// ---------------- K0: fold W_is / biases; write g_Mt[r][16] ----------------
__global__ void k_prep(const float* __restrict__ Wis0, const float* __restrict__ bis0,
                       const float* __restrict__ Wis1, const float* __restrict__ bis1,
                       const float* __restrict__ Wih,  const float* __restrict__ bih,
                       const float* __restrict__ bhh) {
    int r   = blockIdx.x;          // gate row 0..2047
    int tid = threadIdx.x;         // 128
    float acc[16];
#pragma unroll
    for (int j = 0; j < 16; j++) acc[j] = 0.0f;
    const float* wr = Wih + (size_t)r * 1536;      // W_ih row r, cols 0..511
    for (int k = tid; k < 512; k += 128) {
        float w = wr[k];
#pragma unroll
        for (int j = 0; j < 8; j++) acc[j]     += Wis0[k * 8 + j] * w;
#pragma unroll
        for (int j = 0; j < 6; j++) acc[8 + j] += Wis1[k * 6 + j] * w;
        acc[14] += bis0[k] * w;
        acc[15] += bis1[k] * w;
    }
    __shared__ float red[16][128];
#pragma unroll
    for (int j = 0; j < 16; j++) red[j][tid] = acc[j];
    __syncthreads();
    for (int s = 64; s > 0; s >>= 1) {
        if (tid < s) {
#pragma unroll
            for (int j = 0; j < 16; j++) red[j][tid] += red[j][tid + s];
        }
        __syncthreads();
    }
    if (tid < 14) g_Mt[r * 16 + tid] = red[tid][0];
    if (tid == 14) g_Mt[r * 16 + 14] = red[14][0] + bih[r] + bhh[r];
    if (tid == 15) g_Mt[r * 16 + 15] = red[15][0] + bih[r] + bhh[r];
}

// ---------------- K1 merged: temb (blocks 0..8191) | cvtw (8192..10239) | init (10240..10367) ----------------
__global__ void k_pre(const float* __restrict__ x, const float* __restrict__ Wih,
                      const float* __restrict__ h0, const float* __restrict__ c0) {
    int bid = blockIdx.x;
    int tid = threadIdx.x;   // 256
    if (bid < 8192) {
        // timestep embeddings, bf16 hi/lo
        int n = bid;
        float tc = x[n * 16 + 0];
        float tp = x[n * 16 + 1];
        float f  = expf(-9.210340371976184f * (float)tid * (1.0f / 256.0f));
        float s, c;
        __nv_bfloat16* ah = g_Ah + (size_t)n * 1024;
        __nv_bfloat16* al = g_Al + (size_t)n * 1024;
        sincosf(tc * f, &s, &c);
        {
            __nv_bfloat16 h = __float2bfloat16(c);
            ah[tid] = h;        al[tid] = __float2bfloat16(c - __bfloat162float(h));
            h = __float2bfloat16(s);
            ah[256 + tid] = h;  al[256 + tid] = __float2bfloat16(s - __bfloat162float(h));
        }
        sincosf(tp * f, &s, &c);
        {
            __nv_bfloat16 h = __float2bfloat16(c);
            ah[512 + tid] = h;  al[512 + tid] = __float2bfloat16(c - __bfloat162float(h));
            h = __float2bfloat16(s);
            ah[768 + tid] = h;  al[768 + tid] = __float2bfloat16(s - __bfloat162float(h));
        }
    } else if (bid < 10240) {
        // convert W_ih[:,512:1536] to bf16 hi/lo
        int r = bid - 8192;
        for (int k = tid; k < 1024; k += 256) {
            float w = Wih[(size_t)r * 1536 + 512 + k];
            __nv_bfloat16 h = __float2bfloat16(w);
            g_Bh[(size_t)r * 1024 + k] = h;
            g_Bl[(size_t)r * 1024 + k] = __float2bfloat16(w - __bfloat162float(h));
        }
    } else {
        // init h (bf16 hi/lo, [seq][k]) and c (fp32 [k][seq]); reset barrier
        int idx = (bid - 10240) * 256 + tid;     // over 64*512
        if (idx == 0) g_bar = 0u;
        int b = idx >> 9, k = idx & 511;
        float hv = h0[b * 512 + k], cv = c0[b * 512 + k];
        __nv_bfloat16 hi = __float2bfloat16(hv);
        __nv_bfloat16 lo = __float2bfloat16(hv - __bfloat162float(hi));
        g_h0h[(size_t)b * 512 + k] = hi;  g_h0h[(size_t)(64 + b) * 512 + k] = hi;
        g_h0l[(size_t)b * 512 + k] = lo;  g_h0l[(size_t)(64 + b) * 512 + k] = lo;
        g_c[k * 128 + b] = cv;  g_c[k * 128 + 64 + b] = cv;
    }
}

// ---------------- K3: HMMA bf16 GEMM  gin = t_emb @ W_ih[:,512:1536].T (hi/lo split, 3 products) ----------------
// Grid (32, 64): M=128 (batch by), N=64 (bx). 8 warps (2m x 4n), warp tile 64x16.
// 3-stage cp.async pipeline; 2 blocks/SM.
#define MPITCH 40
#define MSTAGE 30720
#define MMA_SMEM (3 * MSTAGE)
__global__ __launch_bounds__(256, 2) void k_mma(const float* __restrict__ x) {
    extern __shared__ char dsm[];
    uint32_t sb = smem_u32(dsm);

    int tid = threadIdx.x;
    int warp = tid >> 5, lane = tid & 31;
    int warp_m = warp >> 2;           // 0..1
    int warp_n = warp & 3;            // 0..3
    int bx = blockIdx.x;              // n-tile 0..31 (64 gate rows each)
    int by = blockIdx.y;              // m-tile == batch b, 0..63

    const __nv_bfloat16* srcA_h = g_Ah + (size_t)by * 128 * 1024;
    const __nv_bfloat16* srcA_l = g_Al + (size_t)by * 128 * 1024;
    const __nv_bfloat16* srcB_h = g_Bh + (size_t)bx * 64 * 1024;
    const __nv_bfloat16* srcB_l = g_Bl + (size_t)bx * 64 * 1024;

    int la7 = lane & 7, lb = (lane >> 3) & 1, lc = lane >> 4;
    int arow = warp_m * 64 + la7 + lb * 8;
    int acol0 = lc * 8;
    int brow = warp_n * 16 + la7 + lc * 8;
    int bcol0 = lb * 8;

    // load addressing
    uint32_t a_off0 = (uint32_t)((tid >> 2) * 80 + (tid & 3) * 16);
    uint32_t a_off1 = a_off0 + 64 * 80;
    size_t a_g0 = (size_t)(tid >> 2) * 1024 + (tid & 3) * 8;
    size_t a_g1 = a_g0 + (size_t)64 * 1024;
    uint32_t b_off = a_off0;                      // rows 0..63
    size_t b_g = a_g0;

#define MISSUE(KC, ST) do {                                                    \
    uint32_t base = sb + (ST) * MSTAGE;                                        \
    size_t gc_ = (size_t)(KC);                                                 \
    CP_ASYNC16(base +         a_off0, srcA_h + a_g0 + gc_);                    \
    CP_ASYNC16(base + 10240 + a_off0, srcA_l + a_g0 + gc_);                    \
    CP_ASYNC16(base +         a_off1, srcA_h + a_g1 + gc_);                    \
    CP_ASYNC16(base + 10240 + a_off1, srcA_l + a_g1 + gc_);                    \
    CP_ASYNC16(base + 20480 + b_off, srcB_h + b_g + gc_);                      \
    CP_ASYNC16(base + 25600 + b_off, srcB_l + b_g + gc_);                      \
    asm volatile("cp.async.commit_group;");                                    \
} while (0)

    float acc[4][2][4];
#pragma unroll
    for (int i = 0; i < 4; i++)
#pragma unroll
        for (int j = 0; j < 2; j++)
#pragma unroll
            for (int q = 0; q < 4; q++) acc[i][j][q] = 0.0f;

    MISSUE(0, 0);
    MISSUE(32, 1);
    for (int kt = 0; kt < 32; kt++) {
        int st = kt % 3;
        if (kt < 30) {
            MISSUE((kt + 2) * 32, (kt + 2) % 3);
            asm volatile("cp.async.wait_group 2;");
        } else if (kt == 30) {
            asm volatile("cp.async.wait_group 1;");
        } else {
            asm volatile("cp.async.wait_group 0;");
        }
        __syncthreads();

        uint32_t uAh = sb + st * MSTAGE;
        uint32_t uAl = uAh + 10240;
        uint32_t uBh = uAh + 20480;
        uint32_t uBl = uAh + 25600;

#pragma unroll
        for (int ks = 0; ks < 2; ks++) {
            uint32_t ah[4][4], al[4][4], bh[2][2], bl[2][2];
            int acol = ks * 16 + acol0;
            int bcol = ks * 16 + bcol0;
#pragma unroll
            for (int mi = 0; mi < 4; mi++) {
                uint32_t off = (uint32_t)(((arow + mi * 16) * MPITCH + acol) * 2);
                ldsm4(ah[mi], uAh + off);
                ldsm4(al[mi], uAl + off);
            }
            {
                uint32_t off = (uint32_t)((brow * MPITCH + bcol) * 2);
                uint32_t r[4];
                ldsm4(r, uBh + off);
                bh[0][0] = r[0]; bh[0][1] = r[1]; bh[1][0] = r[2]; bh[1][1] = r[3];
                ldsm4(r, uBl + off);
                bl[0][0] = r[0]; bl[0][1] = r[1]; bl[1][0] = r[2]; bl[1][1] = r[3];
            }
#pragma unroll
            for (int mi = 0; mi < 4; mi++)
#pragma unroll
                for (int ni = 0; ni < 2; ni++) {
                    mma16816(acc[mi][ni], ah[mi], bh[ni]);
                    mma16816(acc[mi][ni], ah[mi], bl[ni]);
                    mma16816(acc[mi][ni], al[mi], bh[ni]);
                }
        }
        __syncthreads();
    }
#undef MISSUE

    int gr = lane >> 2, gc = (lane & 3) * 2;
#pragma unroll
    for (int mi = 0; mi < 4; mi++) {
#pragma unroll
        for (int half = 0; half < 2; half++) {
            int m = warp_m * 64 + mi * 16 + gr + half * 8;   // original timestep t
            int s2 = m >> 6;
            int t0 = 2 * (m & 63);
            int seq = s2 * 64 + by;
            const float* xr = x + ((size_t)(by * 128 + m)) * 16 + 2;
            float xs[14];
#pragma unroll
            for (int jj = 0; jj < 14; jj++) xs[jj] = xr[jj];
            float* g0 = g_gin + ((size_t)t0 * 128 + seq) * 2048 + bx * 64;
            float* g1 = g0 + (size_t)128 * 2048;
#pragma unroll
            for (int ni = 0; ni < 2; ni++) {
                int lcol = warp_n * 16 + ni * 8 + gc;
                int r = bx * 64 + lcol;
                float b0 = acc[mi][ni][half * 2 + 0];
                float b1 = acc[mi][ni][half * 2 + 1];
                float v0a, v1a, v0b, v1b;
                {
                    const float4* mt = (const float4*)(g_Mt + (size_t)r * 16);
                    float4 m0 = mt[0], m1 = mt[1], m2 = mt[2], m3 = mt[3];
                    v0a = b0 + m3.z + xs[0]*m0.x + xs[1]*m0.y + xs[2]*m0.z + xs[3]*m0.w
                               + xs[4]*m1.x + xs[5]*m1.y + xs[6]*m1.z + xs[7]*m1.w;
                    v1a = b0 + m3.w + xs[8]*m2.x + xs[9]*m2.y + xs[10]*m2.z + xs[11]*m2.w
                               + xs[12]*m3.x + xs[13]*m3.y;
                }
                {
                    const float4* mt = (const float4*)(g_Mt + (size_t)(r + 1) * 16);
                    float4 m0 = mt[0], m1 = mt[1], m2 = mt[2], m3 = mt[3];
                    v0b = b1 + m3.z + xs[0]*m0.x + xs[1]*m0.y + xs[2]*m0.z + xs[3]*m0.w
                               + xs[4]*m1.x + xs[5]*m1.y + xs[6]*m1.z + xs[7]*m1.w;
                    v1b = b1 + m3.w + xs[8]*m2.x + xs[9]*m2.y + xs[10]*m2.z + xs[11]*m2.w
                               + xs[12]*m3.x + xs[13]*m3.y;
                }
                *(float2*)(g0 + lcol) = make_float2(v0a, v0b);
                *(float2*)(g1 + lcol) = make_float2(v1a, v1b);
            }
        }
    }
}

// ---------------- K4: persistent HMMA LSTM recurrence ----------------
// 128 blocks = 32 unit-groups x 4 seq-groups. Block owns 16 units (64 gate rows,
// a = g*16+u) x 32 seqs. A = W_hh rows bf16 hi/lo in smem (static, 133 KB).
// B = h[32 seqs] bf16 hi/lo streamed per step via double-buffered cp.async
// (64 KB/step/block vs 256 KB before -> 4x less L2 traffic).
// 8 warps = 4 m-groups x 2 n-groups; warp tile M16 x N16.
#define AP 520                          // A smem pitch (bf16 elems)
#define BP 136                          // B smem pitch (bf16 elems)
#define GP 36                           // gsm pitch (floats)
#define SA_H 0
#define SA_L 66560
#define SB_H0 133120
#define SB_L0 141824
#define SB_H1 150528
#define SB_L1 159232
#define SGM   167936
#define RNN_SMEM 177152

__global__ __launch_bounds__(256) void k_rnn(const float* __restrict__ Whh) {
    extern __shared__ char sm[];
    uint32_t sb = smem_u32(sm);
    __nv_bfloat16* sAh = (__nv_bfloat16*)(sm + SA_H);
    __nv_bfloat16* sAl = (__nv_bfloat16*)(sm + SA_L);
    float* gsm = (float*)(sm + SGM);

    int tid = threadIdx.x, warp = tid >> 5, lane = tid & 31;
    int ug = blockIdx.x >> 2, sg = blockIdx.x & 3;
    int j16 = ug * 16;                 // unit base
    int s32 = sg * 32;                 // seq base
    int wm = warp & 3, wn = warp >> 2; // warp tile coords

    // Stage A: 64 W_hh rows (a = g*16+u -> global row g*512 + j16 + u) bf16 hi/lo, once.
    for (int i = tid; i < 64 * 512; i += 256) {
        int a = i >> 9, k = i & 511;
        float w = Whh[(size_t)((a >> 4) * 512 + j16 + (a & 15)) * 512 + k];
        __nv_bfloat16 hi = __float2bfloat16(w);
        sAh[a * AP + k] = hi;
        sAl[a * AP + k] = __float2bfloat16(w - __bfloat162float(hi));
    }

    // Cell-state ownership: thread -> (units j16+u0, j16+u0+1; seq gseq)
    int sl = tid & 31;
    int u0 = (tid >> 5) * 2;           // 0..14
    int gseq = s32 + sl;
    float cc[2];
    cc[0] = g_c[(j16 + u0) * 128 + gseq];
    cc[1] = g_c[(j16 + u0 + 1) * 128 + gseq];
    __syncthreads();

    int la7 = lane & 7, lb2 = (lane >> 3) & 1, lc2 = lane >> 4;
    int arow = wm * 16 + la7 + lb2 * 8;
    int acol0 = lc2 * 8;
    int brow = wn * 16 + la7 + lc2 * 8;
    int bcol0 = lb2 * 8;
    uint32_t bufH[2] = {sb + SB_H0, sb + SB_H1};
    uint32_t bufL[2] = {sb + SB_L0, sb + SB_L1};

#define ISSUE_CHUNK(KC, BUF) do {                                              \
    _Pragma("unroll")                                                          \
    for (int j = 0; j < 2; j++) {                                              \
        int gidx = tid * 2 + j;                                                \
        int row = gidx >> 4, seg = gidx & 15;                                  \
        uint32_t so = (uint32_t)(row * (BP * 2) + seg * 16);                   \
        size_t go_ = (size_t)(s32 + row) * 512 + (size_t)(KC) * 128 + seg * 8; \
        CP_ASYNC16(bufH[BUF] + so, srcH + go_);                                \
        CP_ASYNC16(bufL[BUF] + so, srcL + go_);                                \
    }                                                                          \
    asm volatile("cp.async.commit_group;");                                    \
} while (0)

    for (int t = 0; t < 128; t++) {
        const __nv_bfloat16* srcH = (t == 0) ? g_h0h : (g_hhh + (size_t)(t - 1) * 65536);
        const __nv_bfloat16* srcL = (t == 0) ? g_h0l : (g_hhl + (size_t)(t - 1) * 65536);

        ISSUE_CHUNK(0, 0);

        // Hoisted gin loads: independent of h, overlap their latency with the MMA loop.
        const float* ginb = g_gin + ((size_t)t * 128 + gseq) * 2048 + j16 + u0;
        float2 xi = *(const float2*)(ginb);
        float2 xf = *(const float2*)(ginb + 512);
        float2 xg = *(const float2*)(ginb + 1024);
        float2 xo = *(const float2*)(ginb + 1536);

        float acc0[4] = {0, 0, 0, 0}, acc1[4] = {0, 0, 0, 0};

        for (int kc4 = 0; kc4 < 4; kc4++) {
            int cb = kc4 & 1;
            if (kc4 < 3) {
                ISSUE_CHUNK(kc4 + 1, cb ^ 1);
                asm volatile("cp.async.wait_group 1;");
            } else {
                asm volatile("cp.async.wait_group 0;");
            }
            __syncthreads();
#pragma unroll
            for (int ks = 0; ks < 8; ks++) {
                int acol = kc4 * 128 + ks * 16 + acol0;
                uint32_t aoff = (uint32_t)((arow * AP + acol) * 2);
                uint32_t ah[4], al[4];
                ldsm4(ah, sb + SA_H + aoff);
                ldsm4(al, sb + SA_L + aoff);
                uint32_t boff = (uint32_t)((brow * BP + bcol0 + ks * 16) * 2);
                uint32_t r[4], bh0[2], bh1[2], bl0[2], bl1[2];
                ldsm4(r, bufH[cb] + boff);
                bh0[0] = r[0]; bh0[1] = r[1]; bh1[0] = r[2]; bh1[1] = r[3];
                ldsm4(r, bufL[cb] + boff);
                bl0[0] = r[0]; bl0[1] = r[1]; bl1[0] = r[2]; bl1[1] = r[3];
                mma16816(acc0, ah, bh0);
                mma16816(acc0, ah, bl0);
                mma16816(acc0, al, bh0);
                mma16816(acc1, ah, bh1);
                mma16816(acc1, ah, bl1);
                mma16816(acc1, al, bh1);
            }
            __syncthreads();
        }

        // Store gate sums to gsm[a][sl]: rows wm*16+{gr,gr+8}, cols wn*16 + gc (+8)
        int gr = lane >> 2, gc = (lane & 3) * 2;
        *(float2*)&gsm[(wm * 16 + gr) * GP + wn * 16 + gc]         = make_float2(acc0[0], acc0[1]);
        *(float2*)&gsm[(wm * 16 + gr + 8) * GP + wn * 16 + gc]     = make_float2(acc0[2], acc0[3]);
        *(float2*)&gsm[(wm * 16 + gr) * GP + wn * 16 + 8 + gc]     = make_float2(acc1[0], acc1[1]);
        *(float2*)&gsm[(wm * 16 + gr + 8) * GP + wn * 16 + 8 + gc] = make_float2(acc1[2], acc1[3]);
        __syncthreads();

        // Update phase: thread handles (seq=gseq, units u0, u0+1); gate g row = g*16+u
        float xiv[2] = {xi.x, xi.y};
        float xfv[2] = {xf.x, xf.y};
        float xgv[2] = {xg.x, xg.y};
        float xov[2] = {xo.x, xo.y};
        float hn[2];
#pragma unroll
        for (int q = 0; q < 2; q++) {
            int u = u0 + q;
            float gi = gsm[u * GP + sl]        + xiv[q];
            float gf = gsm[(16 + u) * GP + sl] + xfv[q];
            float gg = gsm[(32 + u) * GP + sl] + xgv[q];
            float go = gsm[(48 + u) * GP + sl] + xov[q];
            cc[q] = sigf(gf) * cc[q] + sigf(gi) * tanhf(gg);
            hn[q] = sigf(go) * tanhf(cc[q]);
        }
        __align__(4) __nv_bfloat16 hhv[2], hlv[2];
#pragma unroll
        for (int q = 0; q < 2; q++) {
            __nv_bfloat16 hi = __float2bfloat16(hn[q]);
            hhv[q] = hi;
            hlv[q] = __float2bfloat16(hn[q] - __bfloat162float(hi));
        }
        size_t hb = ((size_t)t * 128 + gseq) * 512 + j16 + u0;
        *(uint32_t*)(g_hhh + hb) = *(uint32_t*)hhv;
        *(uint32_t*)(g_hhl + hb) = *(uint32_t*)hlv;

        if (t < 127) {
            __syncthreads();
            if (tid == 0) {
                __threadfence();
                atomicAdd(&g_bar, 1u);
                unsigned target = (unsigned)(t + 1) * RNN_BLOCKS;
                volatile unsigned int* vb = &g_bar;
                while (*vb < target) { }
            }
            __syncthreads();
        }
    }
#undef ISSUE_CHUNK
}

// ---------------- K5: gather h at lengths-1 (hi+lo), output linear + sigmoid ----------------
__global__ void k_out(const float* __restrict__ Wo, const float* __restrict__ bo,
                      const int* __restrict__ lengths, float* __restrict__ out) {
    int b = blockIdx.x, o = blockIdx.y;
    int tid = threadIdx.x;             // 128
    int t = lengths[b] - 1;
    const __nv_bfloat16* ph = g_hhh + (size_t)t * 65536;
    const __nv_bfloat16* pl = g_hhl + (size_t)t * 65536;
    float acc = 0.0f;
    for (int k = tid; k < 512; k += 128) {
        float h0v = __bfloat162float(ph[(size_t)b * 512 + k])
                  + __bfloat162float(pl[(size_t)b * 512 + k]);
        float h1v = __bfloat162float(ph[(size_t)(64 + b) * 512 + k])
                  + __bfloat162float(pl[(size_t)(64 + b) * 512 + k]);
        acc += Wo[o * 1024 + k] * h0v + Wo[o * 1024 + 512 + k] * h1v;
    }
    __shared__ float red[128];
    red[tid] = acc;
    __syncthreads();
    for (int s = 64; s > 0; s >>= 1) {
        if (tid < s) red[tid] += red[tid + s];
        __syncthreads();
    }
    if (tid == 0) out[b * 14 + o] = 1.0f / (1.0f + expf(-(red[0] + bo[o])));
}

// ---------------- launch ----------------
extern "C" void kernel_launch(void* const* d_in, const int* in_sizes, int n_in,
                              void* d_out, int out_size) {
    const float* x     = (const float*)d_in[0];
    const int*   len   = (const int*)  d_in[1];
    const float* h0    = (const float*)d_in[2];
    const float* c0    = (const float*)d_in[3];
    const float* Wis0  = (const float*)d_in[4];
    const float* bis0  = (const float*)d_in[5];
    const float* Wis1  = (const float*)d_in[6];
    const float* bis1  = (const float*)d_in[7];
    const float* Wih   = (const float*)d_in[8];
    const float* Whh   = (const float*)d_in[9];
    const float* bih   = (const float*)d_in[10];
    const float* bhh   = (const float*)d_in[11];
    const float* Wo    = (const float*)d_in[12];
    const float* bo    = (const float*)d_in[13];
    float* out = (float*)d_out;

    cudaFuncSetAttribute(k_rnn, cudaFuncAttributeMaxDynamicSharedMemorySize, RNN_SMEM);
    cudaFuncSetAttribute(k_mma, cudaFuncAttributeMaxDynamicSharedMemorySize, MMA_SMEM);

    k_prep<<<2048, 128>>>(Wis0, bis0, Wis1, bis1, Wih, bih, bhh);
    k_pre<<<10368, 256>>>(x, Wih, h0, c0);
    k_mma<<<dim3(32, 64), 256, MMA_SMEM>>>(x);
    k_rnn<<<RNN_BLOCKS, 256, RNN_SMEM>>>(Whh);
    k_out<<<dim3(64, 14), 128>>>(Wo, bo, len, out);
}